// round 13
// baseline (speedup 1.0000x reference)
#include <cuda_runtime.h>
#include <cuda_bf16.h>
#include <cuda_fp16.h>
#include <math.h>
#include <stdint.h>

// Problem constants (MinGRUCell: B=8, T=4096, D=256, H=256)
#define BB 8
#define TT 4096
#define DD 256
#define HH 256
#define MM (BB * TT)          // 32768 rows
#define NN 512                // logical N: gate(256) + update(256)

// Chunked scan config
#define NCH 128
#define CLEN 32               // NCH*CLEN == TT

// tcgen05 only exists in the arch-specific compilation pass.
#if defined(__CUDA_ARCH_FEAT_SM103_ALL) || defined(__CUDA_ARCH_FEAT_SM100_ALL) || defined(__CUDA_ARCH_FEAT_SM101_ALL)
#define HAS_TCGEN05 1
#else
#define HAS_TCGEN05 0
#endif

// Scratch: gate/update streams in fp16 (halves DRAM traffic; ~3e-4 rel err)
__device__ __half g_scratch[(size_t)MM * HH];
__device__ __half u_scratch[(size_t)MM * HH];
__device__ float chunkA[(size_t)BB * NCH * HH];
__device__ float chunkB[(size_t)BB * NCH * HH];
__device__ float hstart[(size_t)BB * NCH * HH];
// Pre-split weights: rows 0..255 = Wz, 256..511 = Wh   [NN, DD] bf16
__device__ __nv_bfloat16 Wcat_hi[(size_t)NN * DD];
__device__ __nv_bfloat16 Wcat_lo[(size_t)NN * DD];
// Pre-split activations [MM, DD] bf16
__device__ __nv_bfloat16 x_hi[(size_t)MM * DD];
__device__ __nv_bfloat16 x_lo[(size_t)MM * DD];

// ---------------------------------------------------------------------------
// PTX helpers
// ---------------------------------------------------------------------------
__device__ __forceinline__ uint32_t smem_u32(const void* p) {
    uint32_t a;
    asm("{ .reg .u64 t; cvta.to.shared.u64 t, %1; cvt.u32.u64 %0, t; }"
        : "=r"(a) : "l"(p));
    return a;
}

#define SW128(o) ((o) ^ (((o) >> 3) & 0x70))

static constexpr uint64_t SMEM_DESC_BASE_SW128_C =
    (uint64_t(2)  << 61) | (uint64_t(1) << 46) | (uint64_t(64) << 32) | (uint64_t(1) << 16);
#define MK_DESC(addr) (SMEM_DESC_BASE_SW128_C | ((uint64_t)((addr) >> 4) & 0x3FFF))

#define CP_ASYNC16(dst, src) \
    asm volatile("cp.async.cg.shared.global [%0], [%1], 16;" :: "r"(dst), "l"(src) : "memory")
#define CP_COMMIT()  asm volatile("cp.async.commit_group;" ::: "memory")
#define CP_WAIT0()   asm volatile("cp.async.wait_group 0;" ::: "memory")

#if HAS_TCGEN05
#define TC_ALLOC(sm, n)  asm volatile("tcgen05.alloc.cta_group::1.sync.aligned.shared::cta.b32 [%0], %1;" :: "r"((uint32_t)(sm)), "r"((uint32_t)(n)) : "memory")
#define TC_DEALLOC(t, n) asm volatile("tcgen05.dealloc.cta_group::1.sync.aligned.b32 %0, %1;" :: "r"(t), "r"((uint32_t)(n)))
#define TC_RELINQ()      asm volatile("tcgen05.relinquish_alloc_permit.cta_group::1.sync.aligned;")
#define TC_COMMIT(mb)    asm volatile("tcgen05.commit.cta_group::1.mbarrier::arrive::one.shared::cluster.b64 [%0];" :: "r"((uint32_t)(mb)) : "memory")
#define TC_WAIT_LD()     asm volatile("tcgen05.wait::ld.sync.aligned;" ::: "memory")
#define TC_FENCE_AFTER() asm volatile("tcgen05.fence::after_thread_sync;" ::: "memory")
#define FENCE_ASYNC()    asm volatile("fence.proxy.async.shared::cta;" ::: "memory")
#define MBAR_INIT(mb, c) asm volatile("mbarrier.init.shared.b64 [%0], %1;" :: "r"((uint32_t)(mb)), "r"((uint32_t)(c)) : "memory")

#define MBAR_WAIT(mb, ph) do {                                                 \
    uint32_t _m = (uint32_t)(mb), _p = (uint32_t)(ph), _d;                     \
    asm volatile("{\n\t.reg .pred p;\n\t"                                      \
        "mbarrier.try_wait.parity.acquire.cta.shared::cta.b64 p, [%1], %2;\n\t"\
        "selp.b32 %0, 1, 0, p;\n\t}"                                           \
        : "=r"(_d) : "r"(_m), "r"(_p) : "memory");                             \
    if (!_d) {                                                                 \
        asm volatile("{\n\t.reg .pred P1;\n\t"                                 \
            "WL_%=:\n\t"                                                       \
            "mbarrier.try_wait.parity.acquire.cta.shared::cta.b64 P1, [%0], %1, 0x989680;\n\t" \
            "@P1 bra.uni WD_%=;\n\t"                                           \
            "bra.uni WL_%=;\n\t"                                               \
            "WD_%=:\n\t}"                                                      \
            :: "r"(_m), "r"(_p) : "memory");                                   \
    }                                                                          \
} while (0)

#define LDTM32(r, ta)                                                          \
    asm volatile("tcgen05.ld.sync.aligned.32x32b.x32.b32 "                     \
        "{%0,%1,%2,%3,%4,%5,%6,%7,%8,%9,%10,%11,%12,%13,%14,%15,"              \
        "%16,%17,%18,%19,%20,%21,%22,%23,%24,%25,%26,%27,%28,%29,%30,%31}, [%32];" \
        : "=r"((r)[0]),"=r"((r)[1]),"=r"((r)[2]),"=r"((r)[3]),                 \
          "=r"((r)[4]),"=r"((r)[5]),"=r"((r)[6]),"=r"((r)[7]),                 \
          "=r"((r)[8]),"=r"((r)[9]),"=r"((r)[10]),"=r"((r)[11]),               \
          "=r"((r)[12]),"=r"((r)[13]),"=r"((r)[14]),"=r"((r)[15]),             \
          "=r"((r)[16]),"=r"((r)[17]),"=r"((r)[18]),"=r"((r)[19]),             \
          "=r"((r)[20]),"=r"((r)[21]),"=r"((r)[22]),"=r"((r)[23]),             \
          "=r"((r)[24]),"=r"((r)[25]),"=r"((r)[26]),"=r"((r)[27]),             \
          "=r"((r)[28]),"=r"((r)[29]),"=r"((r)[30]),"=r"((r)[31])              \
        : "r"(ta))

__device__ __forceinline__ void mma_f16_ss(uint32_t d, uint64_t a, uint64_t b,
                                           uint32_t idesc, uint32_t en) {
    asm volatile(
        "{\n\t.reg .pred p;\n\tsetp.ne.u32 p, %5, 0;\n\t"
        "tcgen05.mma.cta_group::1.kind::f16 [%0], %1, %2, %3, {%4, %4, %4, %4}, p;\n\t}"
        :: "r"(d), "l"(a), "l"(b), "r"(idesc), "r"(0u), "r"(en) : "memory");
}
#endif // HAS_TCGEN05

// idesc: dtype=F32, atype=BF16, btype=BF16, N=256, M=128
static constexpr uint32_t GEMM_IDESC =
    (1u << 4) | (1u << 7) | (1u << 10) | ((256u / 8) << 17) | ((128u / 16) << 24);

// ---------------------------------------------------------------------------
// Weight pre-split
// ---------------------------------------------------------------------------
__global__ __launch_bounds__(256)
void mingru_wprep_kernel(const float* __restrict__ Wz, const float* __restrict__ Wh)
{
    const int i = blockIdx.x * 256 + threadIdx.x;
    const int n = i >> 8;
    const int d = i & 255;
    float v = (n < HH) ? Wz[n * DD + d] : Wh[(n - HH) * DD + d];
    __nv_bfloat16 hi = __float2bfloat16(v);
    Wcat_hi[i] = hi;
    Wcat_lo[i] = __float2bfloat16(v - __bfloat162float(hi));
}

// ---------------------------------------------------------------------------
// Activation pre-split: x fp32 -> x_hi, x_lo bf16 (one float4 per thread)
// ---------------------------------------------------------------------------
__global__ __launch_bounds__(256)
void mingru_xsplit_kernel(const float* __restrict__ x)
{
    const size_t i4 = (size_t)blockIdx.x * 256 + threadIdx.x;
    float4 v = reinterpret_cast<const float4*>(x)[i4];
    __nv_bfloat16 h0 = __float2bfloat16(v.x);
    __nv_bfloat16 h1 = __float2bfloat16(v.y);
    __nv_bfloat16 h2 = __float2bfloat16(v.z);
    __nv_bfloat16 h3 = __float2bfloat16(v.w);
    __nv_bfloat162 hp0(h0, h1), hp1(h2, h3);
    __nv_bfloat162 lp0(__float2bfloat16(v.x - __bfloat162float(h0)),
                       __float2bfloat16(v.y - __bfloat162float(h1)));
    __nv_bfloat162 lp1(__float2bfloat16(v.z - __bfloat162float(h2)),
                       __float2bfloat16(v.w - __bfloat162float(h3)));
    uint2 hw = make_uint2(*(uint32_t*)&hp0, *(uint32_t*)&hp1);
    uint2 lw = make_uint2(*(uint32_t*)&lp0, *(uint32_t*)&lp1);
    reinterpret_cast<uint2*>(x_hi)[i4] = hw;
    reinterpret_cast<uint2*>(x_lo)[i4] = lw;
}

// ---------------------------------------------------------------------------
// PERSISTENT pipelined tcgen05 GEMM. grid = 128 CTAs; CTA c handles 4 tiles
// tid2 = c + j*128 (j=0..3); tile: nh = tid2&1 (gate/update), m0 = (tid2>>1)*128.
// 16 steps total (tile-major, 4 K-chunks each); 2 SMEM stage buffers;
// TMEM D ping-pong (tile j -> cols (j&1)*256). Step semantics identical to
// the proven R6 loop: issue MMA(s) -> wait commit(s-1) -> load(s+1); at tile
// end additionally wait commit(s) and run the epilogue (overlaps load(s+1)).
// ---------------------------------------------------------------------------
#define KCH 64
#define NTILE 4
#define NSTEP (NTILE * 4)
#define HDR_BZ 1024
#define HDR_BH 2048
#define STAGE0_OFF 4096
#define STAGE_BYTES (96 * 1024)
#define ST_A_HI 0
#define ST_A_LO (16 * 1024)
#define ST_B_HI (32 * 1024)
#define ST_B_LO (64 * 1024)
#define GEMM_SMEM (STAGE0_OFF + 2 * STAGE_BYTES)

__global__ __launch_bounds__(256, 1)
void mingru_gemm_tc(const float* __restrict__ bz,
                    const float* __restrict__ bh)
{
#if HAS_TCGEN05
    extern __shared__ char smem_raw[];
    char* smem = (char*)(((uintptr_t)smem_raw + 1023) & ~(uintptr_t)1023);
    const uint32_t sbase = smem_u32(smem);

    const int tid = threadIdx.x;            // 0..255
    const int cta = blockIdx.x;             // 0..127

    if (tid < 32) TC_ALLOC(sbase + 0, 512);
    if (tid == 0) MBAR_INIT(sbase + 8, 1);
    *reinterpret_cast<float*>(smem + HDR_BZ + tid * 4) = bz[tid];
    *reinterpret_cast<float*>(smem + HDR_BH + tid * 4) = bh[tid];
    __syncthreads();
    uint32_t tmem;
    asm volatile("ld.shared.b32 %0, [%1];" : "=r"(tmem) : "r"(sbase + 0));

    // tile parameters for step s
    auto tile_m0 = [&](int j) { return (((j << 7) + cta) >> 1) * 128; };
    auto tile_nh = [&](int j) { return ((j << 7) + cta) & 1; };

    // ---- stage loader for step s (all 256 threads; 24 cp.async x 16B) ----
    auto load_step = [&](int s) {
        const int j = s >> 2;
        const int kc = s & 3;
        const int m0 = tile_m0(j);
        const int n0 = tile_nh(j) * 256;
        const uint32_t st = sbase + STAGE0_OFF + (s & 1) * STAGE_BYTES;
        const int k0 = kc * KCH;
#pragma unroll
        for (int jj = 0; jj < 4; jj++) {
            const int i = jj * 256 + tid;        // 0..1023
            const int row = i >> 3;
            const int c16 = i & 7;
            const uint32_t off = SW128((uint32_t)(row * 128 + c16 * 16));
            const size_t src = (size_t)(m0 + row) * DD + k0 + c16 * 8;
            CP_ASYNC16(st + ST_A_HI + off, (const char*)&x_hi[src]);
            CP_ASYNC16(st + ST_A_LO + off, (const char*)&x_lo[src]);
        }
#pragma unroll
        for (int jj = 0; jj < 8; jj++) {
            const int i = jj * 256 + tid;        // 0..2047
            const int row = i >> 3;
            const int c16 = i & 7;
            const uint32_t off = SW128((uint32_t)(row * 128 + c16 * 16));
            const size_t src = (size_t)(n0 + row) * DD + k0 + c16 * 8;
            CP_ASYNC16(st + ST_B_HI + off, (const char*)&Wcat_hi[src]);
            CP_ASYNC16(st + ST_B_LO + off, (const char*)&Wcat_lo[src]);
        }
        CP_COMMIT();
    };

    load_step(0);

    for (int s = 0; s < NSTEP; s++) {
        const int j = s >> 2;
        const int kc = s & 3;
        CP_WAIT0();             // stage s loads complete
        __syncthreads();

        if (tid == 0) {
            FENCE_ASYNC();
            const uint32_t st = sbase + STAGE0_OFF + (s & 1) * STAGE_BYTES;
            const uint64_t ahi = MK_DESC(st + ST_A_HI);
            const uint64_t alo = MK_DESC(st + ST_A_LO);
            const uint64_t bhi = MK_DESC(st + ST_B_HI);
            const uint64_t blo = MK_DESC(st + ST_B_LO);
            const uint64_t ad[3] = { ahi, alo, ahi };
            const uint64_t bd[3] = { bhi, bhi, blo };
            const uint32_t dreg = tmem + (j & 1) * 256;
#pragma unroll
            for (int p = 0; p < 3; p++)
#pragma unroll
                for (int ks = 0; ks < 4; ks++)
                    mma_f16_ss(dreg, ad[p] + ks * 2, bd[p] + ks * 2,
                               GEMM_IDESC, (kc > 0 || p > 0 || ks > 0) ? 1u : 0u);
            TC_COMMIT(sbase + 8);
        }
        // buffer (s+1)&1 was read by MMA s-1 -> wait its commit, then load
        if (s >= 1) MBAR_WAIT(sbase + 8, (s - 1) & 1);
        if (s + 1 < NSTEP) load_step(s + 1);

        if (kc == 3) {
            // tile j's MMA chain done? wait commit(s); epilogue overlaps
            // the already-issued loads of step s+1 (next tile's chunk 0).
            MBAR_WAIT(sbase + 8, s & 1);
            TC_FENCE_AFTER();

            const int m0 = tile_m0(j);
            const bool is_gate = (tile_nh(j) == 0);
            __half* __restrict__ outbuf = is_gate ? g_scratch : u_scratch;
            const float* __restrict__ bias_s = reinterpret_cast<const float*>(
                smem + (is_gate ? HDR_BZ : HDR_BH));
            const uint32_t dreg = tmem + (j & 1) * 256;

            const int w = tid >> 5;
            const int lane = tid & 31;
            const int row = (w & 3) * 32 + lane;
            const int colbase = (w >> 2) * 128;
            __half* __restrict__ orow = outbuf + (size_t)(m0 + row) * HH;
#pragma unroll
            for (int half = 0; half < 2; half++) {
                const int cb = colbase + half * 64;
                uint32_t r[64];
                LDTM32(r, dreg + cb);
                LDTM32(r + 32, dreg + cb + 32);
                TC_WAIT_LD();
#pragma unroll
                for (int q = 0; q < 16; q++) {
                    float4 v;
                    v.x = __uint_as_float(r[q * 4 + 0]) + bias_s[cb + q * 4 + 0];
                    v.y = __uint_as_float(r[q * 4 + 1]) + bias_s[cb + q * 4 + 1];
                    v.z = __uint_as_float(r[q * 4 + 2]) + bias_s[cb + q * 4 + 2];
                    v.w = __uint_as_float(r[q * 4 + 3]) + bias_s[cb + q * 4 + 3];
                    if (is_gate) {
                        v.x = 1.0f / (1.0f + __expf(-v.x));
                        v.y = 1.0f / (1.0f + __expf(-v.y));
                        v.z = 1.0f / (1.0f + __expf(-v.z));
                        v.w = 1.0f / (1.0f + __expf(-v.w));
                    }
                    __half2 p01 = __floats2half2_rn(v.x, v.y);
                    __half2 p23 = __floats2half2_rn(v.z, v.w);
                    uint2 pk = make_uint2(*(uint32_t*)&p01, *(uint32_t*)&p23);
                    *reinterpret_cast<uint2*>(&orow[cb + q * 4]) = pk;
                }
            }
        }
    }

    __syncthreads();
    if (tid < 32) {
        TC_RELINQ();
        TC_DEALLOC(tmem, 512);
    }
#endif // HAS_TCGEN05
}

// ---------------------------------------------------------------------------
// Scan pass 1: compose CLEN affine steps per (b, chunk, h-pair) into (A, B).
// half2 lanes (two h per thread) + 8-deep batched loads for MLP.
// ---------------------------------------------------------------------------
__global__ __launch_bounds__(256)
void mingru_scan_pass1(void)
{
    const int idx = blockIdx.x * blockDim.x + threadIdx.x;  // 0..131071
    const int h2 = idx & 127;                // h pair index
    const int c = (idx >> 7) & (NCH - 1);
    const int b = idx >> 14;

    const size_t base2 = (((size_t)b * TT + (size_t)c * CLEN) * HH) / 2 + h2;
    const __half2* __restrict__ gp = reinterpret_cast<const __half2*>(g_scratch) + base2;
    const __half2* __restrict__ up = reinterpret_cast<const __half2*>(u_scratch) + base2;

    float A0 = 1.0f, B0 = 0.0f, A1 = 1.0f, B1 = 0.0f;
#pragma unroll
    for (int t0 = 0; t0 < CLEN; t0 += 8) {
        float2 g[8], u[8];
#pragma unroll
        for (int j = 0; j < 8; j++) {
            const size_t off = (size_t)(t0 + j) * (HH / 2);
            g[j] = __half22float2(gp[off]);
            u[j] = __half22float2(up[off]);
        }
#pragma unroll
        for (int j = 0; j < 8; j++) {
            float a0 = 1.0f - g[j].x;
            float a1 = 1.0f - g[j].y;
            B0 = fmaf(a0, B0, g[j].x * u[j].x);
            B1 = fmaf(a1, B1, g[j].y * u[j].y);
            A0 *= a0;
            A1 *= a1;
        }
    }
    const size_t ci = ((size_t)b * NCH + c) * HH + h2 * 2;
    *reinterpret_cast<float2*>(&chunkA[ci]) = make_float2(A0, A1);
    *reinterpret_cast<float2*>(&chunkB[ci]) = make_float2(B0, B1);
}

// ---------------------------------------------------------------------------
// Scan pass 2 (warp-parallel): one warp per (b,h). Lane l composes chunks
// [4l, 4l+4), warp-scan of affine pairs, exclusive prefix applies h0, then
// each lane writes hstart for its 4 chunks.
// ---------------------------------------------------------------------------
__global__ __launch_bounds__(256)
void mingru_scan_pass2(const float* __restrict__ h0)
{
    const int gw = (blockIdx.x * blockDim.x + threadIdx.x) >> 5;  // warp 0..2047
    const int lane = threadIdx.x & 31;
    const int b = gw >> 8;
    const int h = gw & (HH - 1);

    const size_t cb0 = (size_t)b * NCH * HH + h;

    // compose lane's 4 chunks (in t order)
    float a[4], bb[4];
#pragma unroll
    for (int j = 0; j < 4; j++) {
        const size_t ci = cb0 + (size_t)(lane * 4 + j) * HH;
        a[j]  = chunkA[ci];
        bb[j] = chunkB[ci];
    }
    float A = a[0], Bv = bb[0];
#pragma unroll
    for (int j = 1; j < 4; j++) {       // later ∘ earlier
        Bv = fmaf(a[j], Bv, bb[j]);
        A  = a[j] * A;
    }

    // inclusive warp scan of affine pairs over lanes
    float Ai = A, Bi = Bv;
#pragma unroll
    for (int d = 1; d < 32; d <<= 1) {
        float Ad = __shfl_up_sync(0xffffffffu, Ai, d);
        float Bd = __shfl_up_sync(0xffffffffu, Bi, d);
        if (lane >= d) { Bi = fmaf(Ai, Bd, Bi); Ai *= Ad; }
    }
    // exclusive prefix = inclusive of lane-1 (identity for lane 0)
    float Ae = __shfl_up_sync(0xffffffffu, Ai, 1);
    float Be = __shfl_up_sync(0xffffffffu, Bi, 1);
    if (lane == 0) { Ae = 1.0f; Be = 0.0f; }

    float hc = fmaf(Ae, h0[b * HH + h], Be);
#pragma unroll
    for (int j = 0; j < 4; j++) {
        const size_t ci = cb0 + (size_t)(lane * 4 + j) * HH;
        hstart[ci] = hc;
        hc = fmaf(a[j], hc, bb[j]);
    }
}

// ---------------------------------------------------------------------------
// Scan pass 3: replay each chunk from its start state; half2 lanes +
// 8-deep batched loads; fp32 output.
// ---------------------------------------------------------------------------
__global__ __launch_bounds__(256)
void mingru_scan_pass3(float* __restrict__ out)
{
    const int idx = blockIdx.x * blockDim.x + threadIdx.x;  // 0..131071
    const int h2 = idx & 127;
    const int c = (idx >> 7) & (NCH - 1);
    const int b = idx >> 14;

    const size_t base = ((size_t)b * TT + (size_t)c * CLEN) * HH + h2 * 2;
    const size_t base2 = base / 2;
    const __half2* __restrict__ gp = reinterpret_cast<const __half2*>(g_scratch) + base2;
    const __half2* __restrict__ up = reinterpret_cast<const __half2*>(u_scratch) + base2;
    float2* __restrict__ op = reinterpret_cast<float2*>(out + base);

    const size_t ci = ((size_t)b * NCH + c) * HH + h2 * 2;
    float2 hs = *reinterpret_cast<const float2*>(&hstart[ci]);
    float hc0 = hs.x, hc1 = hs.y;

#pragma unroll
    for (int t0 = 0; t0 < CLEN; t0 += 8) {
        float2 g[8], u[8];
#pragma unroll
        for (int j = 0; j < 8; j++) {
            const size_t off = (size_t)(t0 + j) * (HH / 2);
            g[j] = __half22float2(gp[off]);
            u[j] = __half22float2(up[off]);
        }
#pragma unroll
        for (int j = 0; j < 8; j++) {
            hc0 = fmaf(g[j].x, u[j].x - hc0, hc0);
            hc1 = fmaf(g[j].y, u[j].y - hc1, hc1);
            op[(size_t)(t0 + j) * (HH / 2)] = make_float2(hc0, hc1);
        }
    }
}

extern "C" void kernel_launch(void* const* d_in, const int* in_sizes, int n_in,
                              void* d_out, int out_size)
{
    const float* x  = (const float*)d_in[0];   // [B,T,D]
    const float* h0 = (const float*)d_in[1];   // [B,H]
    const float* Wz = (const float*)d_in[2];   // [H,D]
    const float* bz = (const float*)d_in[3];   // [H]
    const float* Wh = (const float*)d_in[4];   // [H,D]
    const float* bh = (const float*)d_in[5];   // [H]
    float* out = (float*)d_out;                // [B,T,H]

    cudaFuncSetAttribute(mingru_gemm_tc,
                         cudaFuncAttributeMaxDynamicSharedMemorySize, GEMM_SMEM);

    mingru_wprep_kernel<<<NN * DD / 256, 256>>>(Wz, Wh);
    mingru_xsplit_kernel<<<MM * DD / 4 / 256, 256>>>(x);

    mingru_gemm_tc<<<128, 256, GEMM_SMEM>>>(bz, bh);

    const int pair_threads = BB * NCH * HH / 2;   // 131072
    mingru_scan_pass1<<<pair_threads / 256, 256>>>();
    mingru_scan_pass2<<<BB * HH * 32 / 256, 256>>>(h0);
    mingru_scan_pass3<<<pair_threads / 256, 256>>>(out);
}

// round 14
// speedup vs baseline: 1.0473x; 1.0473x over previous
#include <cuda_runtime.h>
#include <cuda_bf16.h>
#include <cuda_fp16.h>
#include <math.h>
#include <stdint.h>

// Problem constants (MinGRUCell: B=8, T=4096, D=256, H=256)
#define BB 8
#define TT 4096
#define DD 256
#define HH 256
#define MM (BB * TT)          // 32768 rows
#define NN 512                // logical N: gate(256) + update(256)

// Chunked scan config
#define NCH 128
#define CLEN 32               // NCH*CLEN == TT

// tcgen05 only exists in the arch-specific compilation pass.
#if defined(__CUDA_ARCH_FEAT_SM103_ALL) || defined(__CUDA_ARCH_FEAT_SM100_ALL) || defined(__CUDA_ARCH_FEAT_SM101_ALL)
#define HAS_TCGEN05 1
#else
#define HAS_TCGEN05 0
#endif

// Scratch: gate/update streams in fp16 (halves DRAM traffic; ~3e-4 rel err)
__device__ __half g_scratch[(size_t)MM * HH];
__device__ __half u_scratch[(size_t)MM * HH];
__device__ float chunkA[(size_t)BB * NCH * HH];
__device__ float chunkB[(size_t)BB * NCH * HH];
__device__ float hstart[(size_t)BB * NCH * HH];
// Pre-split weights: rows 0..255 = Wz, 256..511 = Wh   [NN, DD] bf16
__device__ __nv_bfloat16 Wcat_hi[(size_t)NN * DD];
__device__ __nv_bfloat16 Wcat_lo[(size_t)NN * DD];
// Pre-split activations [MM, DD] bf16
__device__ __nv_bfloat16 x_hi[(size_t)MM * DD];
__device__ __nv_bfloat16 x_lo[(size_t)MM * DD];

// ---------------------------------------------------------------------------
// PTX helpers
// ---------------------------------------------------------------------------
__device__ __forceinline__ uint32_t smem_u32(const void* p) {
    uint32_t a;
    asm("{ .reg .u64 t; cvta.to.shared.u64 t, %1; cvt.u32.u64 %0, t; }"
        : "=r"(a) : "l"(p));
    return a;
}

#define SW128(o) ((o) ^ (((o) >> 3) & 0x70))

static constexpr uint64_t SMEM_DESC_BASE_SW128_C =
    (uint64_t(2)  << 61) | (uint64_t(1) << 46) | (uint64_t(64) << 32) | (uint64_t(1) << 16);
#define MK_DESC(addr) (SMEM_DESC_BASE_SW128_C | ((uint64_t)((addr) >> 4) & 0x3FFF))

#define CP_ASYNC16(dst, src) \
    asm volatile("cp.async.cg.shared.global [%0], [%1], 16;" :: "r"(dst), "l"(src) : "memory")
#define CP_COMMIT()  asm volatile("cp.async.commit_group;" ::: "memory")
#define CP_WAIT0()   asm volatile("cp.async.wait_group 0;" ::: "memory")

#if HAS_TCGEN05
#define TC_ALLOC(sm, n)  asm volatile("tcgen05.alloc.cta_group::1.sync.aligned.shared::cta.b32 [%0], %1;" :: "r"((uint32_t)(sm)), "r"((uint32_t)(n)) : "memory")
#define TC_DEALLOC(t, n) asm volatile("tcgen05.dealloc.cta_group::1.sync.aligned.b32 %0, %1;" :: "r"(t), "r"((uint32_t)(n)))
#define TC_RELINQ()      asm volatile("tcgen05.relinquish_alloc_permit.cta_group::1.sync.aligned;")
#define TC_COMMIT(mb)    asm volatile("tcgen05.commit.cta_group::1.mbarrier::arrive::one.shared::cluster.b64 [%0];" :: "r"((uint32_t)(mb)) : "memory")
#define TC_WAIT_LD()     asm volatile("tcgen05.wait::ld.sync.aligned;" ::: "memory")
#define TC_FENCE_AFTER() asm volatile("tcgen05.fence::after_thread_sync;" ::: "memory")
#define FENCE_ASYNC()    asm volatile("fence.proxy.async.shared::cta;" ::: "memory")
#define MBAR_INIT(mb, c) asm volatile("mbarrier.init.shared.b64 [%0], %1;" :: "r"((uint32_t)(mb)), "r"((uint32_t)(c)) : "memory")

#define MBAR_WAIT(mb, ph) do {                                                 \
    uint32_t _m = (uint32_t)(mb), _p = (uint32_t)(ph), _d;                     \
    asm volatile("{\n\t.reg .pred p;\n\t"                                      \
        "mbarrier.try_wait.parity.acquire.cta.shared::cta.b64 p, [%1], %2;\n\t"\
        "selp.b32 %0, 1, 0, p;\n\t}"                                           \
        : "=r"(_d) : "r"(_m), "r"(_p) : "memory");                             \
    if (!_d) {                                                                 \
        asm volatile("{\n\t.reg .pred P1;\n\t"                                 \
            "WL_%=:\n\t"                                                       \
            "mbarrier.try_wait.parity.acquire.cta.shared::cta.b64 P1, [%0], %1, 0x989680;\n\t" \
            "@P1 bra.uni WD_%=;\n\t"                                           \
            "bra.uni WL_%=;\n\t"                                               \
            "WD_%=:\n\t}"                                                      \
            :: "r"(_m), "r"(_p) : "memory");                                   \
    }                                                                          \
} while (0)

#define LDTM32(r, ta)                                                          \
    asm volatile("tcgen05.ld.sync.aligned.32x32b.x32.b32 "                     \
        "{%0,%1,%2,%3,%4,%5,%6,%7,%8,%9,%10,%11,%12,%13,%14,%15,"              \
        "%16,%17,%18,%19,%20,%21,%22,%23,%24,%25,%26,%27,%28,%29,%30,%31}, [%32];" \
        : "=r"((r)[0]),"=r"((r)[1]),"=r"((r)[2]),"=r"((r)[3]),                 \
          "=r"((r)[4]),"=r"((r)[5]),"=r"((r)[6]),"=r"((r)[7]),                 \
          "=r"((r)[8]),"=r"((r)[9]),"=r"((r)[10]),"=r"((r)[11]),               \
          "=r"((r)[12]),"=r"((r)[13]),"=r"((r)[14]),"=r"((r)[15]),             \
          "=r"((r)[16]),"=r"((r)[17]),"=r"((r)[18]),"=r"((r)[19]),             \
          "=r"((r)[20]),"=r"((r)[21]),"=r"((r)[22]),"=r"((r)[23]),             \
          "=r"((r)[24]),"=r"((r)[25]),"=r"((r)[26]),"=r"((r)[27]),             \
          "=r"((r)[28]),"=r"((r)[29]),"=r"((r)[30]),"=r"((r)[31])              \
        : "r"(ta))

__device__ __forceinline__ void mma_f16_ss(uint32_t d, uint64_t a, uint64_t b,
                                           uint32_t idesc, uint32_t en) {
    asm volatile(
        "{\n\t.reg .pred p;\n\tsetp.ne.u32 p, %5, 0;\n\t"
        "tcgen05.mma.cta_group::1.kind::f16 [%0], %1, %2, %3, {%4, %4, %4, %4}, p;\n\t}"
        :: "r"(d), "l"(a), "l"(b), "r"(idesc), "r"(0u), "r"(en) : "memory");
}
#endif // HAS_TCGEN05

// idesc: dtype=F32, atype=BF16, btype=BF16, N=256, M=128
static constexpr uint32_t GEMM_IDESC =
    (1u << 4) | (1u << 7) | (1u << 10) | ((256u / 8) << 17) | ((128u / 16) << 24);

// ---------------------------------------------------------------------------
// Weight pre-split
// ---------------------------------------------------------------------------
__global__ __launch_bounds__(256)
void mingru_wprep_kernel(const float* __restrict__ Wz, const float* __restrict__ Wh)
{
    const int i = blockIdx.x * 256 + threadIdx.x;
    const int n = i >> 8;
    const int d = i & 255;
    float v = (n < HH) ? Wz[n * DD + d] : Wh[(n - HH) * DD + d];
    __nv_bfloat16 hi = __float2bfloat16(v);
    Wcat_hi[i] = hi;
    Wcat_lo[i] = __float2bfloat16(v - __bfloat162float(hi));
}

// ---------------------------------------------------------------------------
// Activation pre-split: x fp32 -> x_hi, x_lo bf16 (one float4 per thread)
// ---------------------------------------------------------------------------
__global__ __launch_bounds__(256)
void mingru_xsplit_kernel(const float* __restrict__ x)
{
    const size_t i4 = (size_t)blockIdx.x * 256 + threadIdx.x;
    float4 v = reinterpret_cast<const float4*>(x)[i4];
    __nv_bfloat16 h0 = __float2bfloat16(v.x);
    __nv_bfloat16 h1 = __float2bfloat16(v.y);
    __nv_bfloat16 h2 = __float2bfloat16(v.z);
    __nv_bfloat16 h3 = __float2bfloat16(v.w);
    __nv_bfloat162 hp0(h0, h1), hp1(h2, h3);
    __nv_bfloat162 lp0(__float2bfloat16(v.x - __bfloat162float(h0)),
                       __float2bfloat16(v.y - __bfloat162float(h1)));
    __nv_bfloat162 lp1(__float2bfloat16(v.z - __bfloat162float(h2)),
                       __float2bfloat16(v.w - __bfloat162float(h3)));
    uint2 hw = make_uint2(*(uint32_t*)&hp0, *(uint32_t*)&hp1);
    uint2 lw = make_uint2(*(uint32_t*)&lp0, *(uint32_t*)&lp1);
    reinterpret_cast<uint2*>(x_hi)[i4] = hw;
    reinterpret_cast<uint2*>(x_lo)[i4] = lw;
}

// ---------------------------------------------------------------------------
// Pipelined tcgen05 GEMM (R12 exact, measured best). CTA: M=128, N=256
// (gate or update), K=256 in 4 chunks of 64. 2-stage cp.async double
// buffering. grid = (2, 256), 256 threads, 1 CTA/SM. Epilogue stores fp16.
// ---------------------------------------------------------------------------
#define KCH 64
#define NKC (DD / KCH)          // 4
#define HDR_BIAS 16
#define STAGE0_OFF 2048
#define STAGE_BYTES (96 * 1024)
#define ST_A_HI 0
#define ST_A_LO (16 * 1024)
#define ST_B_HI (32 * 1024)
#define ST_B_LO (64 * 1024)
#define GEMM_SMEM (STAGE0_OFF + 2 * STAGE_BYTES + 1024)

__global__ __launch_bounds__(256, 1)
void mingru_gemm_tc(const float* __restrict__ bz,
                    const float* __restrict__ bh)
{
#if HAS_TCGEN05
    extern __shared__ char smem_raw[];
    char* smem = (char*)(((uintptr_t)smem_raw + 1023) & ~(uintptr_t)1023);
    const uint32_t sbase = smem_u32(smem);

    const int tid = threadIdx.x;            // 0..255
    const int m0 = blockIdx.y * 128;
    const bool is_gate = (blockIdx.x == 0);
    const int n0 = blockIdx.x * 256;        // row offset into Wcat
    const float* __restrict__ bias = is_gate ? bz : bh;
    __half* __restrict__ outbuf = is_gate ? g_scratch : u_scratch;

    if (tid < 32) TC_ALLOC(sbase + 0, 256);
    if (tid == 0) MBAR_INIT(sbase + 8, 1);
    *reinterpret_cast<float*>(smem + HDR_BIAS + tid * 4) = bias[tid];
    __syncthreads();
    uint32_t tmem;
    asm volatile("ld.shared.b32 %0, [%1];" : "=r"(tmem) : "r"(sbase + 0));

    // ---- stage loader: 24 cp.async x 16B per thread ----
    auto load_stage = [&](int s, int kc) {
        const uint32_t st = sbase + STAGE0_OFF + s * STAGE_BYTES;
        const int k0 = kc * KCH;
#pragma unroll
        for (int j = 0; j < 4; j++) {
            const int i = j * 256 + tid;         // 0..1023
            const int row = i >> 3;
            const int c16 = i & 7;
            const uint32_t off = SW128((uint32_t)(row * 128 + c16 * 16));
            const size_t src = (size_t)(m0 + row) * DD + k0 + c16 * 8;
            CP_ASYNC16(st + ST_A_HI + off, (const char*)&x_hi[src]);
            CP_ASYNC16(st + ST_A_LO + off, (const char*)&x_lo[src]);
        }
#pragma unroll
        for (int j = 0; j < 8; j++) {
            const int i = j * 256 + tid;         // 0..2047
            const int row = i >> 3;
            const int c16 = i & 7;
            const uint32_t off = SW128((uint32_t)(row * 128 + c16 * 16));
            const size_t src = (size_t)(n0 + row) * DD + k0 + c16 * 8;
            CP_ASYNC16(st + ST_B_HI + off, (const char*)&Wcat_hi[src]);
            CP_ASYNC16(st + ST_B_LO + off, (const char*)&Wcat_lo[src]);
        }
        CP_COMMIT();
    };

    load_stage(0, 0);

    for (int kc = 0; kc < NKC; kc++) {
        const int s = kc & 1;
        CP_WAIT0();             // stage kc loads complete
        __syncthreads();

        if (tid == 0) {
            FENCE_ASYNC();
            const uint32_t st = sbase + STAGE0_OFF + s * STAGE_BYTES;
            const uint64_t ahi = MK_DESC(st + ST_A_HI);
            const uint64_t alo = MK_DESC(st + ST_A_LO);
            const uint64_t bhi = MK_DESC(st + ST_B_HI);
            const uint64_t blo = MK_DESC(st + ST_B_LO);
            const uint64_t ad[3] = { ahi, alo, ahi };
            const uint64_t bd[3] = { bhi, bhi, blo };
#pragma unroll
            for (int p = 0; p < 3; p++)
#pragma unroll
                for (int ks = 0; ks < 4; ks++)
                    mma_f16_ss(tmem, ad[p] + ks * 2, bd[p] + ks * 2,
                               GEMM_IDESC, (kc > 0 || p > 0 || ks > 0) ? 1u : 0u);
            TC_COMMIT(sbase + 8);
        }
        if (kc >= 1) MBAR_WAIT(sbase + 8, (kc - 1) & 1);  // MMA(kc-1) done -> buffer free
        if (kc + 1 < NKC) load_stage(s ^ 1, kc + 1);
    }
    MBAR_WAIT(sbase + 8, (NKC - 1) & 1);   // MMA(last) done
    TC_FENCE_AFTER();

    // ---- Epilogue: warp w -> rows (w&3)*32+lane, cols (w>>2)*128 .. +128.
    //      Bias (+sigmoid for gate), pack fp16, 8B stores.
    {
        const int w = tid >> 5;
        const int lane = tid & 31;
        const int row = (w & 3) * 32 + lane;
        const int colbase = (w >> 2) * 128;
        __half* __restrict__ orow = outbuf + (size_t)(m0 + row) * HH;
        const float* __restrict__ bias_s = reinterpret_cast<const float*>(smem + HDR_BIAS);
#pragma unroll
        for (int half = 0; half < 2; half++) {
            const int cb = colbase + half * 64;
            uint32_t r[64];
            LDTM32(r, tmem + cb);
            LDTM32(r + 32, tmem + cb + 32);
            TC_WAIT_LD();
#pragma unroll
            for (int q = 0; q < 16; q++) {
                float4 v;
                v.x = __uint_as_float(r[q * 4 + 0]) + bias_s[cb + q * 4 + 0];
                v.y = __uint_as_float(r[q * 4 + 1]) + bias_s[cb + q * 4 + 1];
                v.z = __uint_as_float(r[q * 4 + 2]) + bias_s[cb + q * 4 + 2];
                v.w = __uint_as_float(r[q * 4 + 3]) + bias_s[cb + q * 4 + 3];
                if (is_gate) {
                    v.x = 1.0f / (1.0f + __expf(-v.x));
                    v.y = 1.0f / (1.0f + __expf(-v.y));
                    v.z = 1.0f / (1.0f + __expf(-v.z));
                    v.w = 1.0f / (1.0f + __expf(-v.w));
                }
                __half2 p01 = __floats2half2_rn(v.x, v.y);
                __half2 p23 = __floats2half2_rn(v.z, v.w);
                uint2 pk = make_uint2(*(uint32_t*)&p01, *(uint32_t*)&p23);
                *reinterpret_cast<uint2*>(&orow[cb + q * 4]) = pk;
            }
        }
    }

    __syncthreads();
    if (tid < 32) {
        TC_RELINQ();
        TC_DEALLOC(tmem, 256);
    }
#endif // HAS_TCGEN05
}

// ---------------------------------------------------------------------------
// Scan pass 1: compose CLEN affine steps per (b, chunk, h-pair) into (A, B).
// half2 lanes (two h per thread) + 8-deep batched loads for MLP.
// ---------------------------------------------------------------------------
__global__ __launch_bounds__(256)
void mingru_scan_pass1(void)
{
    const int idx = blockIdx.x * blockDim.x + threadIdx.x;  // 0..131071
    const int h2 = idx & 127;                // h pair index
    const int c = (idx >> 7) & (NCH - 1);
    const int b = idx >> 14;

    const size_t base2 = (((size_t)b * TT + (size_t)c * CLEN) * HH) / 2 + h2;
    const __half2* __restrict__ gp = reinterpret_cast<const __half2*>(g_scratch) + base2;
    const __half2* __restrict__ up = reinterpret_cast<const __half2*>(u_scratch) + base2;

    float A0 = 1.0f, B0 = 0.0f, A1 = 1.0f, B1 = 0.0f;
#pragma unroll
    for (int t0 = 0; t0 < CLEN; t0 += 8) {
        float2 g[8], u[8];
#pragma unroll
        for (int j = 0; j < 8; j++) {
            const size_t off = (size_t)(t0 + j) * (HH / 2);
            g[j] = __half22float2(gp[off]);
            u[j] = __half22float2(up[off]);
        }
#pragma unroll
        for (int j = 0; j < 8; j++) {
            float a0 = 1.0f - g[j].x;
            float a1 = 1.0f - g[j].y;
            B0 = fmaf(a0, B0, g[j].x * u[j].x);
            B1 = fmaf(a1, B1, g[j].y * u[j].y);
            A0 *= a0;
            A1 *= a1;
        }
    }
    const size_t ci = ((size_t)b * NCH + c) * HH + h2 * 2;
    *reinterpret_cast<float2*>(&chunkA[ci]) = make_float2(A0, A1);
    *reinterpret_cast<float2*>(&chunkB[ci]) = make_float2(B0, B1);
}

// ---------------------------------------------------------------------------
// Scan pass 2 (warp-parallel, R13 — kept): one warp per (b,h). Lane l
// composes chunks [4l, 4l+4), warp-scan of affine pairs, exclusive prefix
// applies h0, each lane writes hstart for its 4 chunks.
// ---------------------------------------------------------------------------
__global__ __launch_bounds__(256)
void mingru_scan_pass2(const float* __restrict__ h0)
{
    const int gw = (blockIdx.x * blockDim.x + threadIdx.x) >> 5;  // warp 0..2047
    const int lane = threadIdx.x & 31;
    const int b = gw >> 8;
    const int h = gw & (HH - 1);

    const size_t cb0 = (size_t)b * NCH * HH + h;

    // compose lane's 4 chunks (in t order)
    float a[4], bb[4];
#pragma unroll
    for (int j = 0; j < 4; j++) {
        const size_t ci = cb0 + (size_t)(lane * 4 + j) * HH;
        a[j]  = chunkA[ci];
        bb[j] = chunkB[ci];
    }
    float A = a[0], Bv = bb[0];
#pragma unroll
    for (int j = 1; j < 4; j++) {       // later ∘ earlier
        Bv = fmaf(a[j], Bv, bb[j]);
        A  = a[j] * A;
    }

    // inclusive warp scan of affine pairs over lanes
    float Ai = A, Bi = Bv;
#pragma unroll
    for (int d = 1; d < 32; d <<= 1) {
        float Ad = __shfl_up_sync(0xffffffffu, Ai, d);
        float Bd = __shfl_up_sync(0xffffffffu, Bi, d);
        if (lane >= d) { Bi = fmaf(Ai, Bd, Bi); Ai *= Ad; }
    }
    // exclusive prefix = inclusive of lane-1 (identity for lane 0)
    float Ae = __shfl_up_sync(0xffffffffu, Ai, 1);
    float Be = __shfl_up_sync(0xffffffffu, Bi, 1);
    if (lane == 0) { Ae = 1.0f; Be = 0.0f; }

    float hc = fmaf(Ae, h0[b * HH + h], Be);
#pragma unroll
    for (int j = 0; j < 4; j++) {
        const size_t ci = cb0 + (size_t)(lane * 4 + j) * HH;
        hstart[ci] = hc;
        hc = fmaf(a[j], hc, bb[j]);
    }
}

// ---------------------------------------------------------------------------
// Scan pass 3: replay each chunk from its start state; half2 lanes +
// 8-deep batched loads; fp32 output.
// ---------------------------------------------------------------------------
__global__ __launch_bounds__(256)
void mingru_scan_pass3(float* __restrict__ out)
{
    const int idx = blockIdx.x * blockDim.x + threadIdx.x;  // 0..131071
    const int h2 = idx & 127;
    const int c = (idx >> 7) & (NCH - 1);
    const int b = idx >> 14;

    const size_t base = ((size_t)b * TT + (size_t)c * CLEN) * HH + h2 * 2;
    const size_t base2 = base / 2;
    const __half2* __restrict__ gp = reinterpret_cast<const __half2*>(g_scratch) + base2;
    const __half2* __restrict__ up = reinterpret_cast<const __half2*>(u_scratch) + base2;
    float2* __restrict__ op = reinterpret_cast<float2*>(out + base);

    const size_t ci = ((size_t)b * NCH + c) * HH + h2 * 2;
    float2 hs = *reinterpret_cast<const float2*>(&hstart[ci]);
    float hc0 = hs.x, hc1 = hs.y;

#pragma unroll
    for (int t0 = 0; t0 < CLEN; t0 += 8) {
        float2 g[8], u[8];
#pragma unroll
        for (int j = 0; j < 8; j++) {
            const size_t off = (size_t)(t0 + j) * (HH / 2);
            g[j] = __half22float2(gp[off]);
            u[j] = __half22float2(up[off]);
        }
#pragma unroll
        for (int j = 0; j < 8; j++) {
            hc0 = fmaf(g[j].x, u[j].x - hc0, hc0);
            hc1 = fmaf(g[j].y, u[j].y - hc1, hc1);
            op[(size_t)(t0 + j) * (HH / 2)] = make_float2(hc0, hc1);
        }
    }
}

extern "C" void kernel_launch(void* const* d_in, const int* in_sizes, int n_in,
                              void* d_out, int out_size)
{
    const float* x  = (const float*)d_in[0];   // [B,T,D]
    const float* h0 = (const float*)d_in[1];   // [B,H]
    const float* Wz = (const float*)d_in[2];   // [H,D]
    const float* bz = (const float*)d_in[3];   // [H]
    const float* Wh = (const float*)d_in[4];   // [H,D]
    const float* bh = (const float*)d_in[5];   // [H]
    float* out = (float*)d_out;                // [B,T,H]

    cudaFuncSetAttribute(mingru_gemm_tc,
                         cudaFuncAttributeMaxDynamicSharedMemorySize, GEMM_SMEM);

    mingru_wprep_kernel<<<NN * DD / 256, 256>>>(Wz, Wh);
    mingru_xsplit_kernel<<<MM * DD / 4 / 256, 256>>>(x);

    dim3 grid(2, MM / 128);
    mingru_gemm_tc<<<grid, 256, GEMM_SMEM>>>(bz, bh);

    const int pair_threads = BB * NCH * HH / 2;   // 131072
    mingru_scan_pass1<<<pair_threads / 256, 256>>>();
    mingru_scan_pass2<<<BB * HH * 32 / 256, 256>>>(h0);
    mingru_scan_pass3<<<pair_threads / 256, 256>>>(out);
}

// round 15
// speedup vs baseline: 1.0997x; 1.0501x over previous
#include <cuda_runtime.h>
#include <cuda_bf16.h>
#include <cuda_fp16.h>
#include <math.h>
#include <stdint.h>

// Problem constants (MinGRUCell: B=8, T=4096, D=256, H=256)
#define BB 8
#define TT 4096
#define DD 256
#define HH 256
#define MM (BB * TT)          // 32768 rows
#define NN 512                // logical N: gate(256) + update(256)

// Chunked scan config
#define NCH 128
#define CLEN 32               // NCH*CLEN == TT

// tcgen05 only exists in the arch-specific compilation pass.
#if defined(__CUDA_ARCH_FEAT_SM103_ALL) || defined(__CUDA_ARCH_FEAT_SM100_ALL) || defined(__CUDA_ARCH_FEAT_SM101_ALL)
#define HAS_TCGEN05 1
#else
#define HAS_TCGEN05 0
#endif

// Scratch: gate/update streams in fp16 (halves DRAM traffic)
__device__ __half g_scratch[(size_t)MM * HH];
__device__ __half u_scratch[(size_t)MM * HH];
__device__ float chunkA[(size_t)BB * NCH * HH];
__device__ float chunkB[(size_t)BB * NCH * HH];
__device__ float hstart[(size_t)BB * NCH * HH];
// Weights fp16 single: rows 0..255 = Wz, 256..511 = Wh   [NN, DD]
__device__ __half Wcat_f16[(size_t)NN * DD];
// Activations fp16 split (hi + residual lo): [MM, DD]
__device__ __half x_hi[(size_t)MM * DD];
__device__ __half x_lo[(size_t)MM * DD];

// ---------------------------------------------------------------------------
// PTX helpers
// ---------------------------------------------------------------------------
__device__ __forceinline__ uint32_t smem_u32(const void* p) {
    uint32_t a;
    asm("{ .reg .u64 t; cvta.to.shared.u64 t, %1; cvt.u32.u64 %0, t; }"
        : "=r"(a) : "l"(p));
    return a;
}

#define SW128(o) ((o) ^ (((o) >> 3) & 0x70))

static constexpr uint64_t SMEM_DESC_BASE_SW128_C =
    (uint64_t(2)  << 61) | (uint64_t(1) << 46) | (uint64_t(64) << 32) | (uint64_t(1) << 16);
#define MK_DESC(addr) (SMEM_DESC_BASE_SW128_C | ((uint64_t)((addr) >> 4) & 0x3FFF))

#define CP_ASYNC16(dst, src) \
    asm volatile("cp.async.cg.shared.global [%0], [%1], 16;" :: "r"(dst), "l"(src) : "memory")
#define CP_COMMIT()  asm volatile("cp.async.commit_group;" ::: "memory")
#define CP_WAIT0()   asm volatile("cp.async.wait_group 0;" ::: "memory")

#if HAS_TCGEN05
#define TC_ALLOC(sm, n)  asm volatile("tcgen05.alloc.cta_group::1.sync.aligned.shared::cta.b32 [%0], %1;" :: "r"((uint32_t)(sm)), "r"((uint32_t)(n)) : "memory")
#define TC_DEALLOC(t, n) asm volatile("tcgen05.dealloc.cta_group::1.sync.aligned.b32 %0, %1;" :: "r"(t), "r"((uint32_t)(n)))
#define TC_RELINQ()      asm volatile("tcgen05.relinquish_alloc_permit.cta_group::1.sync.aligned;")
#define TC_COMMIT(mb)    asm volatile("tcgen05.commit.cta_group::1.mbarrier::arrive::one.shared::cluster.b64 [%0];" :: "r"((uint32_t)(mb)) : "memory")
#define TC_WAIT_LD()     asm volatile("tcgen05.wait::ld.sync.aligned;" ::: "memory")
#define TC_FENCE_AFTER() asm volatile("tcgen05.fence::after_thread_sync;" ::: "memory")
#define FENCE_ASYNC()    asm volatile("fence.proxy.async.shared::cta;" ::: "memory")
#define MBAR_INIT(mb, c) asm volatile("mbarrier.init.shared.b64 [%0], %1;" :: "r"((uint32_t)(mb)), "r"((uint32_t)(c)) : "memory")

#define MBAR_WAIT(mb, ph) do {                                                 \
    uint32_t _m = (uint32_t)(mb), _p = (uint32_t)(ph), _d;                     \
    asm volatile("{\n\t.reg .pred p;\n\t"                                      \
        "mbarrier.try_wait.parity.acquire.cta.shared::cta.b64 p, [%1], %2;\n\t"\
        "selp.b32 %0, 1, 0, p;\n\t}"                                           \
        : "=r"(_d) : "r"(_m), "r"(_p) : "memory");                             \
    if (!_d) {                                                                 \
        asm volatile("{\n\t.reg .pred P1;\n\t"                                 \
            "WL_%=:\n\t"                                                       \
            "mbarrier.try_wait.parity.acquire.cta.shared::cta.b64 P1, [%0], %1, 0x989680;\n\t" \
            "@P1 bra.uni WD_%=;\n\t"                                           \
            "bra.uni WL_%=;\n\t"                                               \
            "WD_%=:\n\t}"                                                      \
            :: "r"(_m), "r"(_p) : "memory");                                   \
    }                                                                          \
} while (0)

#define LDTM32(r, ta)                                                          \
    asm volatile("tcgen05.ld.sync.aligned.32x32b.x32.b32 "                     \
        "{%0,%1,%2,%3,%4,%5,%6,%7,%8,%9,%10,%11,%12,%13,%14,%15,"              \
        "%16,%17,%18,%19,%20,%21,%22,%23,%24,%25,%26,%27,%28,%29,%30,%31}, [%32];" \
        : "=r"((r)[0]),"=r"((r)[1]),"=r"((r)[2]),"=r"((r)[3]),                 \
          "=r"((r)[4]),"=r"((r)[5]),"=r"((r)[6]),"=r"((r)[7]),                 \
          "=r"((r)[8]),"=r"((r)[9]),"=r"((r)[10]),"=r"((r)[11]),               \
          "=r"((r)[12]),"=r"((r)[13]),"=r"((r)[14]),"=r"((r)[15]),             \
          "=r"((r)[16]),"=r"((r)[17]),"=r"((r)[18]),"=r"((r)[19]),             \
          "=r"((r)[20]),"=r"((r)[21]),"=r"((r)[22]),"=r"((r)[23]),             \
          "=r"((r)[24]),"=r"((r)[25]),"=r"((r)[26]),"=r"((r)[27]),             \
          "=r"((r)[28]),"=r"((r)[29]),"=r"((r)[30]),"=r"((r)[31])              \
        : "r"(ta))

__device__ __forceinline__ void mma_f16_ss(uint32_t d, uint64_t a, uint64_t b,
                                           uint32_t idesc, uint32_t en) {
    asm volatile(
        "{\n\t.reg .pred p;\n\tsetp.ne.u32 p, %5, 0;\n\t"
        "tcgen05.mma.cta_group::1.kind::f16 [%0], %1, %2, %3, {%4, %4, %4, %4}, p;\n\t}"
        :: "r"(d), "l"(a), "l"(b), "r"(idesc), "r"(0u), "r"(en) : "memory");
}
#endif // HAS_TCGEN05

// idesc: dtype=F32, atype=FP16(0), btype=FP16(0), N=256, M=128
static constexpr uint32_t GEMM_IDESC =
    (1u << 4) | ((256u / 8) << 17) | ((128u / 16) << 24);

// ---------------------------------------------------------------------------
// Weight prep: Wcat_f16 = fp16(concat(Wz, Wh))
// ---------------------------------------------------------------------------
__global__ __launch_bounds__(256)
void mingru_wprep_kernel(const float* __restrict__ Wz, const float* __restrict__ Wh)
{
    const int i = blockIdx.x * 256 + threadIdx.x;
    const int n = i >> 8;
    const int d = i & 255;
    float v = (n < HH) ? Wz[n * DD + d] : Wh[(n - HH) * DD + d];
    Wcat_f16[i] = __float2half_rn(v);
}

// ---------------------------------------------------------------------------
// Activation split: x fp32 -> x_hi + x_lo fp16 (22-bit effective mantissa)
// ---------------------------------------------------------------------------
__global__ __launch_bounds__(256)
void mingru_xsplit_kernel(const float* __restrict__ x)
{
    const size_t i4 = (size_t)blockIdx.x * 256 + threadIdx.x;
    float4 v = reinterpret_cast<const float4*>(x)[i4];
    __half h0 = __float2half_rn(v.x);
    __half h1 = __float2half_rn(v.y);
    __half h2 = __float2half_rn(v.z);
    __half h3 = __float2half_rn(v.w);
    __half2 hp0(h0, h1), hp1(h2, h3);
    __half2 lp0(__float2half_rn(v.x - __half2float(h0)),
                __float2half_rn(v.y - __half2float(h1)));
    __half2 lp1(__float2half_rn(v.z - __half2float(h2)),
                __float2half_rn(v.w - __half2float(h3)));
    uint2 hw = make_uint2(*(uint32_t*)&hp0, *(uint32_t*)&hp1);
    uint2 lw = make_uint2(*(uint32_t*)&lp0, *(uint32_t*)&lp1);
    reinterpret_cast<uint2*>(x_hi)[i4] = hw;
    reinterpret_cast<uint2*>(x_lo)[i4] = lw;
}

// ---------------------------------------------------------------------------
// Pipelined tcgen05 GEMM (R12 skeleton; fp16 2-product). CTA: M=128, N=256
// (gate or update), K=256 in 4 chunks of 64. 2-stage cp.async double
// buffering; stage = A_hi 16K + A_lo 16K + B 32K = 64 KB.
// grid = (2, 256), 256 threads, 1 CTA/SM. Epilogue stores fp16.
// ---------------------------------------------------------------------------
#define KCH 64
#define NKC (DD / KCH)          // 4
#define HDR_BIAS 16
#define STAGE0_OFF 2048
#define STAGE_BYTES (64 * 1024)
#define ST_A_HI 0
#define ST_A_LO (16 * 1024)
#define ST_B    (32 * 1024)
#define GEMM_SMEM (STAGE0_OFF + 2 * STAGE_BYTES + 1024)

__global__ __launch_bounds__(256, 1)
void mingru_gemm_tc(const float* __restrict__ bz,
                    const float* __restrict__ bh)
{
#if HAS_TCGEN05
    extern __shared__ char smem_raw[];
    char* smem = (char*)(((uintptr_t)smem_raw + 1023) & ~(uintptr_t)1023);
    const uint32_t sbase = smem_u32(smem);

    const int tid = threadIdx.x;            // 0..255
    const int m0 = blockIdx.y * 128;
    const bool is_gate = (blockIdx.x == 0);
    const int n0 = blockIdx.x * 256;        // row offset into Wcat
    const float* __restrict__ bias = is_gate ? bz : bh;
    __half* __restrict__ outbuf = is_gate ? g_scratch : u_scratch;

    if (tid < 32) TC_ALLOC(sbase + 0, 256);
    if (tid == 0) MBAR_INIT(sbase + 8, 1);
    *reinterpret_cast<float*>(smem + HDR_BIAS + tid * 4) = bias[tid];
    __syncthreads();
    uint32_t tmem;
    asm volatile("ld.shared.b32 %0, [%1];" : "=r"(tmem) : "r"(sbase + 0));

    // ---- stage loader: 16 cp.async x 16B per thread ----
    auto load_stage = [&](int s, int kc) {
        const uint32_t st = sbase + STAGE0_OFF + s * STAGE_BYTES;
        const int k0 = kc * KCH;
        // A_hi + A_lo: 128 rows x 8 x 16B each
#pragma unroll
        for (int j = 0; j < 4; j++) {
            const int i = j * 256 + tid;         // 0..1023
            const int row = i >> 3;
            const int c16 = i & 7;
            const uint32_t off = SW128((uint32_t)(row * 128 + c16 * 16));
            const size_t src = (size_t)(m0 + row) * DD + k0 + c16 * 8;
            CP_ASYNC16(st + ST_A_HI + off, (const char*)&x_hi[src]);
            CP_ASYNC16(st + ST_A_LO + off, (const char*)&x_lo[src]);
        }
        // B: 256 rows x 8 x 16B
#pragma unroll
        for (int j = 0; j < 8; j++) {
            const int i = j * 256 + tid;         // 0..2047
            const int row = i >> 3;
            const int c16 = i & 7;
            const uint32_t off = SW128((uint32_t)(row * 128 + c16 * 16));
            const size_t src = (size_t)(n0 + row) * DD + k0 + c16 * 8;
            CP_ASYNC16(st + ST_B + off, (const char*)&Wcat_f16[src]);
        }
        CP_COMMIT();
    };

    load_stage(0, 0);

    for (int kc = 0; kc < NKC; kc++) {
        const int s = kc & 1;
        CP_WAIT0();             // stage kc loads complete
        __syncthreads();

        if (tid == 0) {
            FENCE_ASYNC();
            const uint32_t st = sbase + STAGE0_OFF + s * STAGE_BYTES;
            const uint64_t ahi = MK_DESC(st + ST_A_HI);
            const uint64_t alo = MK_DESC(st + ST_A_LO);
            const uint64_t bds = MK_DESC(st + ST_B);
            const uint64_t ad[2] = { ahi, alo };
#pragma unroll
            for (int p = 0; p < 2; p++)
#pragma unroll
                for (int ks = 0; ks < 4; ks++)
                    mma_f16_ss(tmem, ad[p] + ks * 2, bds + ks * 2,
                               GEMM_IDESC, (kc > 0 || p > 0 || ks > 0) ? 1u : 0u);
            TC_COMMIT(sbase + 8);
        }
        if (kc >= 1) MBAR_WAIT(sbase + 8, (kc - 1) & 1);  // MMA(kc-1) done -> buffer free
        if (kc + 1 < NKC) load_stage(s ^ 1, kc + 1);
    }
    MBAR_WAIT(sbase + 8, (NKC - 1) & 1);   // MMA(last) done
    TC_FENCE_AFTER();

    // ---- Epilogue: warp w -> rows (w&3)*32+lane, cols (w>>2)*128 .. +128.
    //      Bias (+sigmoid for gate), pack fp16, 8B stores.
    {
        const int w = tid >> 5;
        const int lane = tid & 31;
        const int row = (w & 3) * 32 + lane;
        const int colbase = (w >> 2) * 128;
        __half* __restrict__ orow = outbuf + (size_t)(m0 + row) * HH;
        const float* __restrict__ bias_s = reinterpret_cast<const float*>(smem + HDR_BIAS);
#pragma unroll
        for (int half = 0; half < 2; half++) {
            const int cb = colbase + half * 64;
            uint32_t r[64];
            LDTM32(r, tmem + cb);
            LDTM32(r + 32, tmem + cb + 32);
            TC_WAIT_LD();
#pragma unroll
            for (int q = 0; q < 16; q++) {
                float4 v;
                v.x = __uint_as_float(r[q * 4 + 0]) + bias_s[cb + q * 4 + 0];
                v.y = __uint_as_float(r[q * 4 + 1]) + bias_s[cb + q * 4 + 1];
                v.z = __uint_as_float(r[q * 4 + 2]) + bias_s[cb + q * 4 + 2];
                v.w = __uint_as_float(r[q * 4 + 3]) + bias_s[cb + q * 4 + 3];
                if (is_gate) {
                    v.x = 1.0f / (1.0f + __expf(-v.x));
                    v.y = 1.0f / (1.0f + __expf(-v.y));
                    v.z = 1.0f / (1.0f + __expf(-v.z));
                    v.w = 1.0f / (1.0f + __expf(-v.w));
                }
                __half2 p01 = __floats2half2_rn(v.x, v.y);
                __half2 p23 = __floats2half2_rn(v.z, v.w);
                uint2 pk = make_uint2(*(uint32_t*)&p01, *(uint32_t*)&p23);
                *reinterpret_cast<uint2*>(&orow[cb + q * 4]) = pk;
            }
        }
    }

    __syncthreads();
    if (tid < 32) {
        TC_RELINQ();
        TC_DEALLOC(tmem, 256);
    }
#endif // HAS_TCGEN05
}

// ---------------------------------------------------------------------------
// Scan pass 1: compose CLEN affine steps per (b, chunk, h-pair) into (A, B).
// half2 lanes (two h per thread) + 8-deep batched loads for MLP.
// ---------------------------------------------------------------------------
__global__ __launch_bounds__(256)
void mingru_scan_pass1(void)
{
    const int idx = blockIdx.x * blockDim.x + threadIdx.x;  // 0..131071
    const int h2 = idx & 127;                // h pair index
    const int c = (idx >> 7) & (NCH - 1);
    const int b = idx >> 14;

    const size_t base2 = (((size_t)b * TT + (size_t)c * CLEN) * HH) / 2 + h2;
    const __half2* __restrict__ gp = reinterpret_cast<const __half2*>(g_scratch) + base2;
    const __half2* __restrict__ up = reinterpret_cast<const __half2*>(u_scratch) + base2;

    float A0 = 1.0f, B0 = 0.0f, A1 = 1.0f, B1 = 0.0f;
#pragma unroll
    for (int t0 = 0; t0 < CLEN; t0 += 8) {
        float2 g[8], u[8];
#pragma unroll
        for (int j = 0; j < 8; j++) {
            const size_t off = (size_t)(t0 + j) * (HH / 2);
            g[j] = __half22float2(gp[off]);
            u[j] = __half22float2(up[off]);
        }
#pragma unroll
        for (int j = 0; j < 8; j++) {
            float a0 = 1.0f - g[j].x;
            float a1 = 1.0f - g[j].y;
            B0 = fmaf(a0, B0, g[j].x * u[j].x);
            B1 = fmaf(a1, B1, g[j].y * u[j].y);
            A0 *= a0;
            A1 *= a1;
        }
    }
    const size_t ci = ((size_t)b * NCH + c) * HH + h2 * 2;
    *reinterpret_cast<float2*>(&chunkA[ci]) = make_float2(A0, A1);
    *reinterpret_cast<float2*>(&chunkB[ci]) = make_float2(B0, B1);
}

// ---------------------------------------------------------------------------
// Scan pass 2 (warp-parallel): one warp per (b,h). Lane l composes chunks
// [4l, 4l+4), warp-scan of affine pairs, exclusive prefix applies h0, then
// each lane writes hstart for its 4 chunks.
// ---------------------------------------------------------------------------
__global__ __launch_bounds__(256)
void mingru_scan_pass2(const float* __restrict__ h0)
{
    const int gw = (blockIdx.x * blockDim.x + threadIdx.x) >> 5;  // warp 0..2047
    const int lane = threadIdx.x & 31;
    const int b = gw >> 8;
    const int h = gw & (HH - 1);

    const size_t cb0 = (size_t)b * NCH * HH + h;

    // compose lane's 4 chunks (in t order)
    float a[4], bb[4];
#pragma unroll
    for (int j = 0; j < 4; j++) {
        const size_t ci = cb0 + (size_t)(lane * 4 + j) * HH;
        a[j]  = chunkA[ci];
        bb[j] = chunkB[ci];
    }
    float A = a[0], Bv = bb[0];
#pragma unroll
    for (int j = 1; j < 4; j++) {       // later ∘ earlier
        Bv = fmaf(a[j], Bv, bb[j]);
        A  = a[j] * A;
    }

    // inclusive warp scan of affine pairs over lanes
    float Ai = A, Bi = Bv;
#pragma unroll
    for (int d = 1; d < 32; d <<= 1) {
        float Ad = __shfl_up_sync(0xffffffffu, Ai, d);
        float Bd = __shfl_up_sync(0xffffffffu, Bi, d);
        if (lane >= d) { Bi = fmaf(Ai, Bd, Bi); Ai *= Ad; }
    }
    // exclusive prefix = inclusive of lane-1 (identity for lane 0)
    float Ae = __shfl_up_sync(0xffffffffu, Ai, 1);
    float Be = __shfl_up_sync(0xffffffffu, Bi, 1);
    if (lane == 0) { Ae = 1.0f; Be = 0.0f; }

    float hc = fmaf(Ae, h0[b * HH + h], Be);
#pragma unroll
    for (int j = 0; j < 4; j++) {
        const size_t ci = cb0 + (size_t)(lane * 4 + j) * HH;
        hstart[ci] = hc;
        hc = fmaf(a[j], hc, bb[j]);
    }
}

// ---------------------------------------------------------------------------
// Scan pass 3: replay each chunk from its start state; half2 lanes +
// 8-deep batched loads; fp32 output.
// ---------------------------------------------------------------------------
__global__ __launch_bounds__(256)
void mingru_scan_pass3(float* __restrict__ out)
{
    const int idx = blockIdx.x * blockDim.x + threadIdx.x;  // 0..131071
    const int h2 = idx & 127;
    const int c = (idx >> 7) & (NCH - 1);
    const int b = idx >> 14;

    const size_t base = ((size_t)b * TT + (size_t)c * CLEN) * HH + h2 * 2;
    const size_t base2 = base / 2;
    const __half2* __restrict__ gp = reinterpret_cast<const __half2*>(g_scratch) + base2;
    const __half2* __restrict__ up = reinterpret_cast<const __half2*>(u_scratch) + base2;
    float2* __restrict__ op = reinterpret_cast<float2*>(out + base);

    const size_t ci = ((size_t)b * NCH + c) * HH + h2 * 2;
    float2 hs = *reinterpret_cast<const float2*>(&hstart[ci]);
    float hc0 = hs.x, hc1 = hs.y;

#pragma unroll
    for (int t0 = 0; t0 < CLEN; t0 += 8) {
        float2 g[8], u[8];
#pragma unroll
        for (int j = 0; j < 8; j++) {
            const size_t off = (size_t)(t0 + j) * (HH / 2);
            g[j] = __half22float2(gp[off]);
            u[j] = __half22float2(up[off]);
        }
#pragma unroll
        for (int j = 0; j < 8; j++) {
            hc0 = fmaf(g[j].x, u[j].x - hc0, hc0);
            hc1 = fmaf(g[j].y, u[j].y - hc1, hc1);
            op[(size_t)(t0 + j) * (HH / 2)] = make_float2(hc0, hc1);
        }
    }
}

extern "C" void kernel_launch(void* const* d_in, const int* in_sizes, int n_in,
                              void* d_out, int out_size)
{
    const float* x  = (const float*)d_in[0];   // [B,T,D]
    const float* h0 = (const float*)d_in[1];   // [B,H]
    const float* Wz = (const float*)d_in[2];   // [H,D]
    const float* bz = (const float*)d_in[3];   // [H]
    const float* Wh = (const float*)d_in[4];   // [H,D]
    const float* bh = (const float*)d_in[5];   // [H]
    float* out = (float*)d_out;                // [B,T,H]

    cudaFuncSetAttribute(mingru_gemm_tc,
                         cudaFuncAttributeMaxDynamicSharedMemorySize, GEMM_SMEM);

    mingru_wprep_kernel<<<NN * DD / 256, 256>>>(Wz, Wh);
    mingru_xsplit_kernel<<<MM * DD / 4 / 256, 256>>>(x);

    dim3 grid(2, MM / 128);
    mingru_gemm_tc<<<grid, 256, GEMM_SMEM>>>(bz, bh);

    const int pair_threads = BB * NCH * HH / 2;   // 131072
    mingru_scan_pass1<<<pair_threads / 256, 256>>>();
    mingru_scan_pass2<<<BB * HH * 32 / 256, 256>>>(h0);
    mingru_scan_pass3<<<pair_threads / 256, 256>>>(out);
}

// round 16
// speedup vs baseline: 1.1454x; 1.0416x over previous
#include <cuda_runtime.h>
#include <cuda_bf16.h>
#include <cuda_fp16.h>
#include <math.h>
#include <stdint.h>

// Problem constants (MinGRUCell: B=8, T=4096, D=256, H=256)
#define BB 8
#define TT 4096
#define DD 256
#define HH 256
#define MM (BB * TT)          // 32768 rows
#define NN 512                // logical N: gate(256) + update(256)

// Chunked scan config
#define NCH 128
#define CLEN 32               // NCH*CLEN == TT

// tcgen05 only exists in the arch-specific compilation pass.
#if defined(__CUDA_ARCH_FEAT_SM103_ALL) || defined(__CUDA_ARCH_FEAT_SM100_ALL) || defined(__CUDA_ARCH_FEAT_SM101_ALL)
#define HAS_TCGEN05 1
#else
#define HAS_TCGEN05 0
#endif

// Scratch: gate/update streams in fp16 (halves DRAM traffic)
__device__ __half g_scratch[(size_t)MM * HH];
__device__ __half u_scratch[(size_t)MM * HH];
__device__ float chunkA[(size_t)BB * NCH * HH];
__device__ float chunkB[(size_t)BB * NCH * HH];
__device__ float hstart[(size_t)BB * NCH * HH];
// Weights fp16: rows 0..255 = Wz, 256..511 = Wh   [NN, DD]
__device__ __half Wcat_f16[(size_t)NN * DD];
// Activations fp16 (single precision level): [MM, DD]
__device__ __half x_f16[(size_t)MM * DD];

// ---------------------------------------------------------------------------
// PTX helpers
// ---------------------------------------------------------------------------
__device__ __forceinline__ uint32_t smem_u32(const void* p) {
    uint32_t a;
    asm("{ .reg .u64 t; cvta.to.shared.u64 t, %1; cvt.u32.u64 %0, t; }"
        : "=r"(a) : "l"(p));
    return a;
}

#define SW128(o) ((o) ^ (((o) >> 3) & 0x70))

static constexpr uint64_t SMEM_DESC_BASE_SW128_C =
    (uint64_t(2)  << 61) | (uint64_t(1) << 46) | (uint64_t(64) << 32) | (uint64_t(1) << 16);
#define MK_DESC(addr) (SMEM_DESC_BASE_SW128_C | ((uint64_t)((addr) >> 4) & 0x3FFF))

#define CP_ASYNC16(dst, src) \
    asm volatile("cp.async.cg.shared.global [%0], [%1], 16;" :: "r"(dst), "l"(src) : "memory")
#define CP_COMMIT()  asm volatile("cp.async.commit_group;" ::: "memory")
#define CP_WAIT0()   asm volatile("cp.async.wait_group 0;" ::: "memory")

#if HAS_TCGEN05
#define TC_ALLOC(sm, n)  asm volatile("tcgen05.alloc.cta_group::1.sync.aligned.shared::cta.b32 [%0], %1;" :: "r"((uint32_t)(sm)), "r"((uint32_t)(n)) : "memory")
#define TC_DEALLOC(t, n) asm volatile("tcgen05.dealloc.cta_group::1.sync.aligned.b32 %0, %1;" :: "r"(t), "r"((uint32_t)(n)))
#define TC_RELINQ()      asm volatile("tcgen05.relinquish_alloc_permit.cta_group::1.sync.aligned;")
#define TC_COMMIT(mb)    asm volatile("tcgen05.commit.cta_group::1.mbarrier::arrive::one.shared::cluster.b64 [%0];" :: "r"((uint32_t)(mb)) : "memory")
#define TC_WAIT_LD()     asm volatile("tcgen05.wait::ld.sync.aligned;" ::: "memory")
#define TC_FENCE_AFTER() asm volatile("tcgen05.fence::after_thread_sync;" ::: "memory")
#define FENCE_ASYNC()    asm volatile("fence.proxy.async.shared::cta;" ::: "memory")
#define MBAR_INIT(mb, c) asm volatile("mbarrier.init.shared.b64 [%0], %1;" :: "r"((uint32_t)(mb)), "r"((uint32_t)(c)) : "memory")

#define MBAR_WAIT(mb, ph) do {                                                 \
    uint32_t _m = (uint32_t)(mb), _p = (uint32_t)(ph), _d;                     \
    asm volatile("{\n\t.reg .pred p;\n\t"                                      \
        "mbarrier.try_wait.parity.acquire.cta.shared::cta.b64 p, [%1], %2;\n\t"\
        "selp.b32 %0, 1, 0, p;\n\t}"                                           \
        : "=r"(_d) : "r"(_m), "r"(_p) : "memory");                             \
    if (!_d) {                                                                 \
        asm volatile("{\n\t.reg .pred P1;\n\t"                                 \
            "WL_%=:\n\t"                                                       \
            "mbarrier.try_wait.parity.acquire.cta.shared::cta.b64 P1, [%0], %1, 0x989680;\n\t" \
            "@P1 bra.uni WD_%=;\n\t"                                           \
            "bra.uni WL_%=;\n\t"                                               \
            "WD_%=:\n\t}"                                                      \
            :: "r"(_m), "r"(_p) : "memory");                                   \
    }                                                                          \
} while (0)

#define LDTM32(r, ta)                                                          \
    asm volatile("tcgen05.ld.sync.aligned.32x32b.x32.b32 "                     \
        "{%0,%1,%2,%3,%4,%5,%6,%7,%8,%9,%10,%11,%12,%13,%14,%15,"              \
        "%16,%17,%18,%19,%20,%21,%22,%23,%24,%25,%26,%27,%28,%29,%30,%31}, [%32];" \
        : "=r"((r)[0]),"=r"((r)[1]),"=r"((r)[2]),"=r"((r)[3]),                 \
          "=r"((r)[4]),"=r"((r)[5]),"=r"((r)[6]),"=r"((r)[7]),                 \
          "=r"((r)[8]),"=r"((r)[9]),"=r"((r)[10]),"=r"((r)[11]),               \
          "=r"((r)[12]),"=r"((r)[13]),"=r"((r)[14]),"=r"((r)[15]),             \
          "=r"((r)[16]),"=r"((r)[17]),"=r"((r)[18]),"=r"((r)[19]),             \
          "=r"((r)[20]),"=r"((r)[21]),"=r"((r)[22]),"=r"((r)[23]),             \
          "=r"((r)[24]),"=r"((r)[25]),"=r"((r)[26]),"=r"((r)[27]),             \
          "=r"((r)[28]),"=r"((r)[29]),"=r"((r)[30]),"=r"((r)[31])              \
        : "r"(ta))

__device__ __forceinline__ void mma_f16_ss(uint32_t d, uint64_t a, uint64_t b,
                                           uint32_t idesc, uint32_t en) {
    asm volatile(
        "{\n\t.reg .pred p;\n\tsetp.ne.u32 p, %5, 0;\n\t"
        "tcgen05.mma.cta_group::1.kind::f16 [%0], %1, %2, %3, {%4, %4, %4, %4}, p;\n\t}"
        :: "r"(d), "l"(a), "l"(b), "r"(idesc), "r"(0u), "r"(en) : "memory");
}
#endif // HAS_TCGEN05

// idesc: dtype=F32, atype=FP16(0), btype=FP16(0), N=256, M=128
static constexpr uint32_t GEMM_IDESC =
    (1u << 4) | ((256u / 8) << 17) | ((128u / 16) << 24);

// ---------------------------------------------------------------------------
// Weight prep: Wcat_f16 = fp16(concat(Wz, Wh))
// ---------------------------------------------------------------------------
__global__ __launch_bounds__(256)
void mingru_wprep_kernel(const float* __restrict__ Wz, const float* __restrict__ Wh)
{
    const int i = blockIdx.x * 256 + threadIdx.x;
    const int n = i >> 8;
    const int d = i & 255;
    float v = (n < HH) ? Wz[n * DD + d] : Wh[(n - HH) * DD + d];
    Wcat_f16[i] = __float2half_rn(v);
}

// ---------------------------------------------------------------------------
// Activation convert: x fp32 -> fp16
// ---------------------------------------------------------------------------
__global__ __launch_bounds__(256)
void mingru_xconv_kernel(const float* __restrict__ x)
{
    const size_t i4 = (size_t)blockIdx.x * 256 + threadIdx.x;
    float4 v = reinterpret_cast<const float4*>(x)[i4];
    __half2 p0 = __floats2half2_rn(v.x, v.y);
    __half2 p1 = __floats2half2_rn(v.z, v.w);
    uint2 pk = make_uint2(*(uint32_t*)&p0, *(uint32_t*)&p1);
    reinterpret_cast<uint2*>(x_f16)[i4] = pk;
}

// ---------------------------------------------------------------------------
// Pipelined tcgen05 GEMM (fp16 single-product). CTA: M=128, N=256 (gate or
// update), K=256 in 4 chunks of 64. 2-stage cp.async double buffering;
// stage = A 16K + B 32K = 48 KB. grid = (2, 256), 256 threads, 1 CTA/SM.
// ---------------------------------------------------------------------------
#define KCH 64
#define NKC (DD / KCH)          // 4
#define HDR_BIAS 16
#define STAGE0_OFF 2048
#define STAGE_BYTES (48 * 1024)
#define ST_A 0
#define ST_B (16 * 1024)
#define GEMM_SMEM (STAGE0_OFF + 2 * STAGE_BYTES + 1024)

__global__ __launch_bounds__(256, 1)
void mingru_gemm_tc(const float* __restrict__ bz,
                    const float* __restrict__ bh)
{
#if HAS_TCGEN05
    extern __shared__ char smem_raw[];
    char* smem = (char*)(((uintptr_t)smem_raw + 1023) & ~(uintptr_t)1023);
    const uint32_t sbase = smem_u32(smem);

    const int tid = threadIdx.x;            // 0..255
    const int m0 = blockIdx.y * 128;
    const bool is_gate = (blockIdx.x == 0);
    const int n0 = blockIdx.x * 256;        // row offset into Wcat
    const float* __restrict__ bias = is_gate ? bz : bh;
    __half* __restrict__ outbuf = is_gate ? g_scratch : u_scratch;

    if (tid < 32) TC_ALLOC(sbase + 0, 256);
    if (tid == 0) MBAR_INIT(sbase + 8, 1);
    *reinterpret_cast<float*>(smem + HDR_BIAS + tid * 4) = bias[tid];
    __syncthreads();
    uint32_t tmem;
    asm volatile("ld.shared.b32 %0, [%1];" : "=r"(tmem) : "r"(sbase + 0));

    // ---- stage loader: 12 cp.async x 16B per thread ----
    auto load_stage = [&](int s, int kc) {
        const uint32_t st = sbase + STAGE0_OFF + s * STAGE_BYTES;
        const int k0 = kc * KCH;
        // A: 128 rows x 8 x 16B
#pragma unroll
        for (int j = 0; j < 4; j++) {
            const int i = j * 256 + tid;         // 0..1023
            const int row = i >> 3;
            const int c16 = i & 7;
            const uint32_t off = SW128((uint32_t)(row * 128 + c16 * 16));
            const size_t src = (size_t)(m0 + row) * DD + k0 + c16 * 8;
            CP_ASYNC16(st + ST_A + off, (const char*)&x_f16[src]);
        }
        // B: 256 rows x 8 x 16B
#pragma unroll
        for (int j = 0; j < 8; j++) {
            const int i = j * 256 + tid;         // 0..2047
            const int row = i >> 3;
            const int c16 = i & 7;
            const uint32_t off = SW128((uint32_t)(row * 128 + c16 * 16));
            const size_t src = (size_t)(n0 + row) * DD + k0 + c16 * 8;
            CP_ASYNC16(st + ST_B + off, (const char*)&Wcat_f16[src]);
        }
        CP_COMMIT();
    };

    load_stage(0, 0);

    for (int kc = 0; kc < NKC; kc++) {
        const int s = kc & 1;
        CP_WAIT0();             // stage kc loads complete
        __syncthreads();

        if (tid == 0) {
            FENCE_ASYNC();
            const uint32_t st = sbase + STAGE0_OFF + s * STAGE_BYTES;
            const uint64_t ads = MK_DESC(st + ST_A);
            const uint64_t bds = MK_DESC(st + ST_B);
#pragma unroll
            for (int ks = 0; ks < 4; ks++)
                mma_f16_ss(tmem, ads + ks * 2, bds + ks * 2,
                           GEMM_IDESC, (kc > 0 || ks > 0) ? 1u : 0u);
            TC_COMMIT(sbase + 8);
        }
        if (kc >= 1) MBAR_WAIT(sbase + 8, (kc - 1) & 1);  // MMA(kc-1) done -> buffer free
        if (kc + 1 < NKC) load_stage(s ^ 1, kc + 1);
    }
    MBAR_WAIT(sbase + 8, (NKC - 1) & 1);   // MMA(last) done
    TC_FENCE_AFTER();

    // ---- Epilogue: warp w -> rows (w&3)*32+lane, cols (w>>2)*128 .. +128.
    //      Bias (+sigmoid for gate), pack fp16, 8B stores.
    {
        const int w = tid >> 5;
        const int lane = tid & 31;
        const int row = (w & 3) * 32 + lane;
        const int colbase = (w >> 2) * 128;
        __half* __restrict__ orow = outbuf + (size_t)(m0 + row) * HH;
        const float* __restrict__ bias_s = reinterpret_cast<const float*>(smem + HDR_BIAS);
#pragma unroll
        for (int half = 0; half < 2; half++) {
            const int cb = colbase + half * 64;
            uint32_t r[64];
            LDTM32(r, tmem + cb);
            LDTM32(r + 32, tmem + cb + 32);
            TC_WAIT_LD();
#pragma unroll
            for (int q = 0; q < 16; q++) {
                float4 v;
                v.x = __uint_as_float(r[q * 4 + 0]) + bias_s[cb + q * 4 + 0];
                v.y = __uint_as_float(r[q * 4 + 1]) + bias_s[cb + q * 4 + 1];
                v.z = __uint_as_float(r[q * 4 + 2]) + bias_s[cb + q * 4 + 2];
                v.w = __uint_as_float(r[q * 4 + 3]) + bias_s[cb + q * 4 + 3];
                if (is_gate) {
                    v.x = 1.0f / (1.0f + __expf(-v.x));
                    v.y = 1.0f / (1.0f + __expf(-v.y));
                    v.z = 1.0f / (1.0f + __expf(-v.z));
                    v.w = 1.0f / (1.0f + __expf(-v.w));
                }
                __half2 p01 = __floats2half2_rn(v.x, v.y);
                __half2 p23 = __floats2half2_rn(v.z, v.w);
                uint2 pk = make_uint2(*(uint32_t*)&p01, *(uint32_t*)&p23);
                *reinterpret_cast<uint2*>(&orow[cb + q * 4]) = pk;
            }
        }
    }

    __syncthreads();
    if (tid < 32) {
        TC_RELINQ();
        TC_DEALLOC(tmem, 256);
    }
#endif // HAS_TCGEN05
}

// ---------------------------------------------------------------------------
// Scan pass 1: compose CLEN affine steps per (b, chunk, h-pair) into (A, B).
// half2 lanes (two h per thread) + 8-deep batched loads for MLP.
// ---------------------------------------------------------------------------
__global__ __launch_bounds__(256)
void mingru_scan_pass1(void)
{
    const int idx = blockIdx.x * blockDim.x + threadIdx.x;  // 0..131071
    const int h2 = idx & 127;                // h pair index
    const int c = (idx >> 7) & (NCH - 1);
    const int b = idx >> 14;

    const size_t base2 = (((size_t)b * TT + (size_t)c * CLEN) * HH) / 2 + h2;
    const __half2* __restrict__ gp = reinterpret_cast<const __half2*>(g_scratch) + base2;
    const __half2* __restrict__ up = reinterpret_cast<const __half2*>(u_scratch) + base2;

    float A0 = 1.0f, B0 = 0.0f, A1 = 1.0f, B1 = 0.0f;
#pragma unroll
    for (int t0 = 0; t0 < CLEN; t0 += 8) {
        float2 g[8], u[8];
#pragma unroll
        for (int j = 0; j < 8; j++) {
            const size_t off = (size_t)(t0 + j) * (HH / 2);
            g[j] = __half22float2(gp[off]);
            u[j] = __half22float2(up[off]);
        }
#pragma unroll
        for (int j = 0; j < 8; j++) {
            float a0 = 1.0f - g[j].x;
            float a1 = 1.0f - g[j].y;
            B0 = fmaf(a0, B0, g[j].x * u[j].x);
            B1 = fmaf(a1, B1, g[j].y * u[j].y);
            A0 *= a0;
            A1 *= a1;
        }
    }
    const size_t ci = ((size_t)b * NCH + c) * HH + h2 * 2;
    *reinterpret_cast<float2*>(&chunkA[ci]) = make_float2(A0, A1);
    *reinterpret_cast<float2*>(&chunkB[ci]) = make_float2(B0, B1);
}

// ---------------------------------------------------------------------------
// Scan pass 2 (warp-parallel): one warp per (b,h). Lane l composes chunks
// [4l, 4l+4), warp-scan of affine pairs, exclusive prefix applies h0, then
// each lane writes hstart for its 4 chunks.
// ---------------------------------------------------------------------------
__global__ __launch_bounds__(256)
void mingru_scan_pass2(const float* __restrict__ h0)
{
    const int gw = (blockIdx.x * blockDim.x + threadIdx.x) >> 5;  // warp 0..2047
    const int lane = threadIdx.x & 31;
    const int b = gw >> 8;
    const int h = gw & (HH - 1);

    const size_t cb0 = (size_t)b * NCH * HH + h;

    // compose lane's 4 chunks (in t order)
    float a[4], bb[4];
#pragma unroll
    for (int j = 0; j < 4; j++) {
        const size_t ci = cb0 + (size_t)(lane * 4 + j) * HH;
        a[j]  = chunkA[ci];
        bb[j] = chunkB[ci];
    }
    float A = a[0], Bv = bb[0];
#pragma unroll
    for (int j = 1; j < 4; j++) {       // later ∘ earlier
        Bv = fmaf(a[j], Bv, bb[j]);
        A  = a[j] * A;
    }

    // inclusive warp scan of affine pairs over lanes
    float Ai = A, Bi = Bv;
#pragma unroll
    for (int d = 1; d < 32; d <<= 1) {
        float Ad = __shfl_up_sync(0xffffffffu, Ai, d);
        float Bd = __shfl_up_sync(0xffffffffu, Bi, d);
        if (lane >= d) { Bi = fmaf(Ai, Bd, Bi); Ai *= Ad; }
    }
    // exclusive prefix = inclusive of lane-1 (identity for lane 0)
    float Ae = __shfl_up_sync(0xffffffffu, Ai, 1);
    float Be = __shfl_up_sync(0xffffffffu, Bi, 1);
    if (lane == 0) { Ae = 1.0f; Be = 0.0f; }

    float hc = fmaf(Ae, h0[b * HH + h], Be);
#pragma unroll
    for (int j = 0; j < 4; j++) {
        const size_t ci = cb0 + (size_t)(lane * 4 + j) * HH;
        hstart[ci] = hc;
        hc = fmaf(a[j], hc, bb[j]);
    }
}

// ---------------------------------------------------------------------------
// Scan pass 3: replay each chunk from its start state; half2 lanes +
// 8-deep batched loads; fp32 output.
// ---------------------------------------------------------------------------
__global__ __launch_bounds__(256)
void mingru_scan_pass3(float* __restrict__ out)
{
    const int idx = blockIdx.x * blockDim.x + threadIdx.x;  // 0..131071
    const int h2 = idx & 127;
    const int c = (idx >> 7) & (NCH - 1);
    const int b = idx >> 14;

    const size_t base = ((size_t)b * TT + (size_t)c * CLEN) * HH + h2 * 2;
    const size_t base2 = base / 2;
    const __half2* __restrict__ gp = reinterpret_cast<const __half2*>(g_scratch) + base2;
    const __half2* __restrict__ up = reinterpret_cast<const __half2*>(u_scratch) + base2;
    float2* __restrict__ op = reinterpret_cast<float2*>(out + base);

    const size_t ci = ((size_t)b * NCH + c) * HH + h2 * 2;
    float2 hs = *reinterpret_cast<const float2*>(&hstart[ci]);
    float hc0 = hs.x, hc1 = hs.y;

#pragma unroll
    for (int t0 = 0; t0 < CLEN; t0 += 8) {
        float2 g[8], u[8];
#pragma unroll
        for (int j = 0; j < 8; j++) {
            const size_t off = (size_t)(t0 + j) * (HH / 2);
            g[j] = __half22float2(gp[off]);
            u[j] = __half22float2(up[off]);
        }
#pragma unroll
        for (int j = 0; j < 8; j++) {
            hc0 = fmaf(g[j].x, u[j].x - hc0, hc0);
            hc1 = fmaf(g[j].y, u[j].y - hc1, hc1);
            op[(size_t)(t0 + j) * (HH / 2)] = make_float2(hc0, hc1);
        }
    }
}

extern "C" void kernel_launch(void* const* d_in, const int* in_sizes, int n_in,
                              void* d_out, int out_size)
{
    const float* x  = (const float*)d_in[0];   // [B,T,D]
    const float* h0 = (const float*)d_in[1];   // [B,H]
    const float* Wz = (const float*)d_in[2];   // [H,D]
    const float* bz = (const float*)d_in[3];   // [H]
    const float* Wh = (const float*)d_in[4];   // [H,D]
    const float* bh = (const float*)d_in[5];   // [H]
    float* out = (float*)d_out;                // [B,T,H]

    cudaFuncSetAttribute(mingru_gemm_tc,
                         cudaFuncAttributeMaxDynamicSharedMemorySize, GEMM_SMEM);

    mingru_wprep_kernel<<<NN * DD / 256, 256>>>(Wz, Wh);
    mingru_xconv_kernel<<<MM * DD / 4 / 256, 256>>>(x);

    dim3 grid(2, MM / 128);
    mingru_gemm_tc<<<grid, 256, GEMM_SMEM>>>(bz, bh);

    const int pair_threads = BB * NCH * HH / 2;   // 131072
    mingru_scan_pass1<<<pair_threads / 256, 256>>>();
    mingru_scan_pass2<<<BB * HH * 32 / 256, 256>>>(h0);
    mingru_scan_pass3<<<pair_threads / 256, 256>>>(out);
}

// round 17
// speedup vs baseline: 1.1489x; 1.0030x over previous
#include <cuda_runtime.h>
#include <cuda_bf16.h>
#include <cuda_fp16.h>
#include <math.h>
#include <stdint.h>

// Problem constants (MinGRUCell: B=8, T=4096, D=256, H=256)
#define BB 8
#define TT 4096
#define DD 256
#define HH 256
#define MM (BB * TT)          // 32768 rows
#define NN 512                // logical N: gate(256) + update(256)

// Chunked scan config
#define NCH 128
#define CLEN 32               // NCH*CLEN == TT

// tcgen05 only exists in the arch-specific compilation pass.
#if defined(__CUDA_ARCH_FEAT_SM103_ALL) || defined(__CUDA_ARCH_FEAT_SM100_ALL) || defined(__CUDA_ARCH_FEAT_SM101_ALL)
#define HAS_TCGEN05 1
#else
#define HAS_TCGEN05 0
#endif

// Scratch: gate/update streams in fp16 (halves DRAM traffic)
__device__ __half g_scratch[(size_t)MM * HH];
__device__ __half u_scratch[(size_t)MM * HH];
__device__ float chunkA[(size_t)BB * NCH * HH];
__device__ float chunkB[(size_t)BB * NCH * HH];
__device__ float hstart[(size_t)BB * NCH * HH];
// Weights fp16: rows 0..255 = Wz, 256..511 = Wh   [NN, DD]
__device__ __half Wcat_f16[(size_t)NN * DD];
// Activations fp16: [MM, DD]
__device__ __half x_f16[(size_t)MM * DD];

// ---------------------------------------------------------------------------
// PTX helpers
// ---------------------------------------------------------------------------
__device__ __forceinline__ uint32_t smem_u32(const void* p) {
    uint32_t a;
    asm("{ .reg .u64 t; cvta.to.shared.u64 t, %1; cvt.u32.u64 %0, t; }"
        : "=r"(a) : "l"(p));
    return a;
}

#define SW128(o) ((o) ^ (((o) >> 3) & 0x70))

static constexpr uint64_t SMEM_DESC_BASE_SW128_C =
    (uint64_t(2)  << 61) | (uint64_t(1) << 46) | (uint64_t(64) << 32) | (uint64_t(1) << 16);
#define MK_DESC(addr) (SMEM_DESC_BASE_SW128_C | ((uint64_t)((addr) >> 4) & 0x3FFF))

#define CP_ASYNC16(dst, src) \
    asm volatile("cp.async.cg.shared.global [%0], [%1], 16;" :: "r"(dst), "l"(src) : "memory")
#define CP_COMMIT()  asm volatile("cp.async.commit_group;" ::: "memory")
#define CP_WAIT0()   asm volatile("cp.async.wait_group 0;" ::: "memory")

#if HAS_TCGEN05
#define TC_ALLOC(sm, n)  asm volatile("tcgen05.alloc.cta_group::1.sync.aligned.shared::cta.b32 [%0], %1;" :: "r"((uint32_t)(sm)), "r"((uint32_t)(n)) : "memory")
#define TC_DEALLOC(t, n) asm volatile("tcgen05.dealloc.cta_group::1.sync.aligned.b32 %0, %1;" :: "r"(t), "r"((uint32_t)(n)))
#define TC_RELINQ()      asm volatile("tcgen05.relinquish_alloc_permit.cta_group::1.sync.aligned;")
#define TC_COMMIT(mb)    asm volatile("tcgen05.commit.cta_group::1.mbarrier::arrive::one.shared::cluster.b64 [%0];" :: "r"((uint32_t)(mb)) : "memory")
#define TC_WAIT_LD()     asm volatile("tcgen05.wait::ld.sync.aligned;" ::: "memory")
#define TC_FENCE_AFTER() asm volatile("tcgen05.fence::after_thread_sync;" ::: "memory")
#define FENCE_ASYNC()    asm volatile("fence.proxy.async.shared::cta;" ::: "memory")
#define MBAR_INIT(mb, c) asm volatile("mbarrier.init.shared.b64 [%0], %1;" :: "r"((uint32_t)(mb)), "r"((uint32_t)(c)) : "memory")

#define MBAR_WAIT(mb, ph) do {                                                 \
    uint32_t _m = (uint32_t)(mb), _p = (uint32_t)(ph), _d;                     \
    asm volatile("{\n\t.reg .pred p;\n\t"                                      \
        "mbarrier.try_wait.parity.acquire.cta.shared::cta.b64 p, [%1], %2;\n\t"\
        "selp.b32 %0, 1, 0, p;\n\t}"                                           \
        : "=r"(_d) : "r"(_m), "r"(_p) : "memory");                             \
    if (!_d) {                                                                 \
        asm volatile("{\n\t.reg .pred P1;\n\t"                                 \
            "WL_%=:\n\t"                                                       \
            "mbarrier.try_wait.parity.acquire.cta.shared::cta.b64 P1, [%0], %1, 0x989680;\n\t" \
            "@P1 bra.uni WD_%=;\n\t"                                           \
            "bra.uni WL_%=;\n\t"                                               \
            "WD_%=:\n\t}"                                                      \
            :: "r"(_m), "r"(_p) : "memory");                                   \
    }                                                                          \
} while (0)

#define LDTM32(r, ta)                                                          \
    asm volatile("tcgen05.ld.sync.aligned.32x32b.x32.b32 "                     \
        "{%0,%1,%2,%3,%4,%5,%6,%7,%8,%9,%10,%11,%12,%13,%14,%15,"              \
        "%16,%17,%18,%19,%20,%21,%22,%23,%24,%25,%26,%27,%28,%29,%30,%31}, [%32];" \
        : "=r"((r)[0]),"=r"((r)[1]),"=r"((r)[2]),"=r"((r)[3]),                 \
          "=r"((r)[4]),"=r"((r)[5]),"=r"((r)[6]),"=r"((r)[7]),                 \
          "=r"((r)[8]),"=r"((r)[9]),"=r"((r)[10]),"=r"((r)[11]),               \
          "=r"((r)[12]),"=r"((r)[13]),"=r"((r)[14]),"=r"((r)[15]),             \
          "=r"((r)[16]),"=r"((r)[17]),"=r"((r)[18]),"=r"((r)[19]),             \
          "=r"((r)[20]),"=r"((r)[21]),"=r"((r)[22]),"=r"((r)[23]),             \
          "=r"((r)[24]),"=r"((r)[25]),"=r"((r)[26]),"=r"((r)[27]),             \
          "=r"((r)[28]),"=r"((r)[29]),"=r"((r)[30]),"=r"((r)[31])              \
        : "r"(ta))

__device__ __forceinline__ void mma_f16_ss(uint32_t d, uint64_t a, uint64_t b,
                                           uint32_t idesc, uint32_t en) {
    asm volatile(
        "{\n\t.reg .pred p;\n\tsetp.ne.u32 p, %5, 0;\n\t"
        "tcgen05.mma.cta_group::1.kind::f16 [%0], %1, %2, %3, {%4, %4, %4, %4}, p;\n\t}"
        :: "r"(d), "l"(a), "l"(b), "r"(idesc), "r"(0u), "r"(en) : "memory");
}
#endif // HAS_TCGEN05

// idesc: dtype=F32, atype=FP16(0), btype=FP16(0), N=256, M=128
static constexpr uint32_t GEMM_IDESC =
    (1u << 4) | ((256u / 8) << 17) | ((128u / 16) << 24);

// ---------------------------------------------------------------------------
// Weight prep: Wcat_f16 = fp16(concat(Wz, Wh))
// ---------------------------------------------------------------------------
__global__ __launch_bounds__(256)
void mingru_wprep_kernel(const float* __restrict__ Wz, const float* __restrict__ Wh)
{
    const int i = blockIdx.x * 256 + threadIdx.x;
    const int n = i >> 8;
    const int d = i & 255;
    float v = (n < HH) ? Wz[n * DD + d] : Wh[(n - HH) * DD + d];
    Wcat_f16[i] = __float2half_rn(v);
}

// ---------------------------------------------------------------------------
// Activation convert: x fp32 -> fp16
// ---------------------------------------------------------------------------
__global__ __launch_bounds__(256)
void mingru_xconv_kernel(const float* __restrict__ x)
{
    const size_t i4 = (size_t)blockIdx.x * 256 + threadIdx.x;
    float4 v = reinterpret_cast<const float4*>(x)[i4];
    __half2 p0 = __floats2half2_rn(v.x, v.y);
    __half2 p1 = __floats2half2_rn(v.z, v.w);
    uint2 pk = make_uint2(*(uint32_t*)&p0, *(uint32_t*)&p1);
    reinterpret_cast<uint2*>(x_f16)[i4] = pk;
}

// ---------------------------------------------------------------------------
// Pipelined tcgen05 GEMM (fp16 single-product, 2 CTAs/SM). CTA: M=128,
// N=256 (gate or update), K=256 in 4 chunks of 64. 2-stage cp.async double
// buffering; stage = A 16K + B 32K = 48 KB. grid = (2, 256), 256 threads.
// Two CTAs per SM hide each other's waits/epilogues; TMEM 2x256 cols fits.
// ---------------------------------------------------------------------------
#define KCH 64
#define NKC (DD / KCH)          // 4
#define HDR_BIAS 16
#define STAGE0_OFF 2048
#define STAGE_BYTES (48 * 1024)
#define ST_A 0
#define ST_B (16 * 1024)
#define GEMM_SMEM (STAGE0_OFF + 2 * STAGE_BYTES + 1024)

__global__ __launch_bounds__(256, 2)
void mingru_gemm_tc(const float* __restrict__ bz,
                    const float* __restrict__ bh)
{
#if HAS_TCGEN05
    extern __shared__ char smem_raw[];
    char* smem = (char*)(((uintptr_t)smem_raw + 1023) & ~(uintptr_t)1023);
    const uint32_t sbase = smem_u32(smem);

    const int tid = threadIdx.x;            // 0..255
    const int m0 = blockIdx.y * 128;
    const bool is_gate = (blockIdx.x == 0);
    const int n0 = blockIdx.x * 256;        // row offset into Wcat
    const float* __restrict__ bias = is_gate ? bz : bh;
    __half* __restrict__ outbuf = is_gate ? g_scratch : u_scratch;

    if (tid < 32) TC_ALLOC(sbase + 0, 256);
    if (tid == 0) MBAR_INIT(sbase + 8, 1);
    *reinterpret_cast<float*>(smem + HDR_BIAS + tid * 4) = bias[tid];
    __syncthreads();
    uint32_t tmem;
    asm volatile("ld.shared.b32 %0, [%1];" : "=r"(tmem) : "r"(sbase + 0));

    // ---- stage loader: 12 cp.async x 16B per thread ----
    auto load_stage = [&](int s, int kc) {
        const uint32_t st = sbase + STAGE0_OFF + s * STAGE_BYTES;
        const int k0 = kc * KCH;
        // A: 128 rows x 8 x 16B
#pragma unroll
        for (int j = 0; j < 4; j++) {
            const int i = j * 256 + tid;         // 0..1023
            const int row = i >> 3;
            const int c16 = i & 7;
            const uint32_t off = SW128((uint32_t)(row * 128 + c16 * 16));
            const size_t src = (size_t)(m0 + row) * DD + k0 + c16 * 8;
            CP_ASYNC16(st + ST_A + off, (const char*)&x_f16[src]);
        }
        // B: 256 rows x 8 x 16B
#pragma unroll
        for (int j = 0; j < 8; j++) {
            const int i = j * 256 + tid;         // 0..2047
            const int row = i >> 3;
            const int c16 = i & 7;
            const uint32_t off = SW128((uint32_t)(row * 128 + c16 * 16));
            const size_t src = (size_t)(n0 + row) * DD + k0 + c16 * 8;
            CP_ASYNC16(st + ST_B + off, (const char*)&Wcat_f16[src]);
        }
        CP_COMMIT();
    };

    load_stage(0, 0);

    for (int kc = 0; kc < NKC; kc++) {
        const int s = kc & 1;
        CP_WAIT0();             // stage kc loads complete
        __syncthreads();

        if (tid == 0) {
            FENCE_ASYNC();
            const uint32_t st = sbase + STAGE0_OFF + s * STAGE_BYTES;
            const uint64_t ads = MK_DESC(st + ST_A);
            const uint64_t bds = MK_DESC(st + ST_B);
#pragma unroll
            for (int ks = 0; ks < 4; ks++)
                mma_f16_ss(tmem, ads + ks * 2, bds + ks * 2,
                           GEMM_IDESC, (kc > 0 || ks > 0) ? 1u : 0u);
            TC_COMMIT(sbase + 8);
        }
        if (kc >= 1) MBAR_WAIT(sbase + 8, (kc - 1) & 1);  // MMA(kc-1) done -> buffer free
        if (kc + 1 < NKC) load_stage(s ^ 1, kc + 1);
    }
    MBAR_WAIT(sbase + 8, (NKC - 1) & 1);   // MMA(last) done
    TC_FENCE_AFTER();

    // ---- Epilogue: warp w -> rows (w&3)*32+lane, cols (w>>2)*128 .. +128.
    //      Bias (+sigmoid for gate), pack fp16, 8B stores.
    {
        const int w = tid >> 5;
        const int lane = tid & 31;
        const int row = (w & 3) * 32 + lane;
        const int colbase = (w >> 2) * 128;
        __half* __restrict__ orow = outbuf + (size_t)(m0 + row) * HH;
        const float* __restrict__ bias_s = reinterpret_cast<const float*>(smem + HDR_BIAS);
#pragma unroll
        for (int half = 0; half < 2; half++) {
            const int cb = colbase + half * 64;
            uint32_t r[64];
            LDTM32(r, tmem + cb);
            LDTM32(r + 32, tmem + cb + 32);
            TC_WAIT_LD();
#pragma unroll
            for (int q = 0; q < 16; q++) {
                float4 v;
                v.x = __uint_as_float(r[q * 4 + 0]) + bias_s[cb + q * 4 + 0];
                v.y = __uint_as_float(r[q * 4 + 1]) + bias_s[cb + q * 4 + 1];
                v.z = __uint_as_float(r[q * 4 + 2]) + bias_s[cb + q * 4 + 2];
                v.w = __uint_as_float(r[q * 4 + 3]) + bias_s[cb + q * 4 + 3];
                if (is_gate) {
                    v.x = 1.0f / (1.0f + __expf(-v.x));
                    v.y = 1.0f / (1.0f + __expf(-v.y));
                    v.z = 1.0f / (1.0f + __expf(-v.z));
                    v.w = 1.0f / (1.0f + __expf(-v.w));
                }
                __half2 p01 = __floats2half2_rn(v.x, v.y);
                __half2 p23 = __floats2half2_rn(v.z, v.w);
                uint2 pk = make_uint2(*(uint32_t*)&p01, *(uint32_t*)&p23);
                *reinterpret_cast<uint2*>(&orow[cb + q * 4]) = pk;
            }
        }
    }

    __syncthreads();
    if (tid < 32) {
        TC_RELINQ();
        TC_DEALLOC(tmem, 256);
    }
#endif // HAS_TCGEN05
}

// ---------------------------------------------------------------------------
// Scan pass 1: compose CLEN affine steps per (b, chunk, h-pair) into (A, B).
// half2 lanes (two h per thread) + 8-deep batched loads for MLP.
// ---------------------------------------------------------------------------
__global__ __launch_bounds__(256)
void mingru_scan_pass1(void)
{
    const int idx = blockIdx.x * blockDim.x + threadIdx.x;  // 0..131071
    const int h2 = idx & 127;                // h pair index
    const int c = (idx >> 7) & (NCH - 1);
    const int b = idx >> 14;

    const size_t base2 = (((size_t)b * TT + (size_t)c * CLEN) * HH) / 2 + h2;
    const __half2* __restrict__ gp = reinterpret_cast<const __half2*>(g_scratch) + base2;
    const __half2* __restrict__ up = reinterpret_cast<const __half2*>(u_scratch) + base2;

    float A0 = 1.0f, B0 = 0.0f, A1 = 1.0f, B1 = 0.0f;
#pragma unroll
    for (int t0 = 0; t0 < CLEN; t0 += 8) {
        float2 g[8], u[8];
#pragma unroll
        for (int j = 0; j < 8; j++) {
            const size_t off = (size_t)(t0 + j) * (HH / 2);
            g[j] = __half22float2(gp[off]);
            u[j] = __half22float2(up[off]);
        }
#pragma unroll
        for (int j = 0; j < 8; j++) {
            float a0 = 1.0f - g[j].x;
            float a1 = 1.0f - g[j].y;
            B0 = fmaf(a0, B0, g[j].x * u[j].x);
            B1 = fmaf(a1, B1, g[j].y * u[j].y);
            A0 *= a0;
            A1 *= a1;
        }
    }
    const size_t ci = ((size_t)b * NCH + c) * HH + h2 * 2;
    *reinterpret_cast<float2*>(&chunkA[ci]) = make_float2(A0, A1);
    *reinterpret_cast<float2*>(&chunkB[ci]) = make_float2(B0, B1);
}

// ---------------------------------------------------------------------------
// Scan pass 2 (warp-parallel): one warp per (b,h). Lane l composes chunks
// [4l, 4l+4), warp-scan of affine pairs, exclusive prefix applies h0, then
// each lane writes hstart for its 4 chunks.
// ---------------------------------------------------------------------------
__global__ __launch_bounds__(256)
void mingru_scan_pass2(const float* __restrict__ h0)
{
    const int gw = (blockIdx.x * blockDim.x + threadIdx.x) >> 5;  // warp 0..2047
    const int lane = threadIdx.x & 31;
    const int b = gw >> 8;
    const int h = gw & (HH - 1);

    const size_t cb0 = (size_t)b * NCH * HH + h;

    // compose lane's 4 chunks (in t order)
    float a[4], bb[4];
#pragma unroll
    for (int j = 0; j < 4; j++) {
        const size_t ci = cb0 + (size_t)(lane * 4 + j) * HH;
        a[j]  = chunkA[ci];
        bb[j] = chunkB[ci];
    }
    float A = a[0], Bv = bb[0];
#pragma unroll
    for (int j = 1; j < 4; j++) {       // later ∘ earlier
        Bv = fmaf(a[j], Bv, bb[j]);
        A  = a[j] * A;
    }

    // inclusive warp scan of affine pairs over lanes
    float Ai = A, Bi = Bv;
#pragma unroll
    for (int d = 1; d < 32; d <<= 1) {
        float Ad = __shfl_up_sync(0xffffffffu, Ai, d);
        float Bd = __shfl_up_sync(0xffffffffu, Bi, d);
        if (lane >= d) { Bi = fmaf(Ai, Bd, Bi); Ai *= Ad; }
    }
    // exclusive prefix = inclusive of lane-1 (identity for lane 0)
    float Ae = __shfl_up_sync(0xffffffffu, Ai, 1);
    float Be = __shfl_up_sync(0xffffffffu, Bi, 1);
    if (lane == 0) { Ae = 1.0f; Be = 0.0f; }

    float hc = fmaf(Ae, h0[b * HH + h], Be);
#pragma unroll
    for (int j = 0; j < 4; j++) {
        const size_t ci = cb0 + (size_t)(lane * 4 + j) * HH;
        hstart[ci] = hc;
        hc = fmaf(a[j], hc, bb[j]);
    }
}

// ---------------------------------------------------------------------------
// Scan pass 3: replay each chunk from its start state; half2 lanes +
// 8-deep batched loads; fp32 output.
// ---------------------------------------------------------------------------
__global__ __launch_bounds__(256)
void mingru_scan_pass3(float* __restrict__ out)
{
    const int idx = blockIdx.x * blockDim.x + threadIdx.x;  // 0..131071
    const int h2 = idx & 127;
    const int c = (idx >> 7) & (NCH - 1);
    const int b = idx >> 14;

    const size_t base = ((size_t)b * TT + (size_t)c * CLEN) * HH + h2 * 2;
    const size_t base2 = base / 2;
    const __half2* __restrict__ gp = reinterpret_cast<const __half2*>(g_scratch) + base2;
    const __half2* __restrict__ up = reinterpret_cast<const __half2*>(u_scratch) + base2;
    float2* __restrict__ op = reinterpret_cast<float2*>(out + base);

    const size_t ci = ((size_t)b * NCH + c) * HH + h2 * 2;
    float2 hs = *reinterpret_cast<const float2*>(&hstart[ci]);
    float hc0 = hs.x, hc1 = hs.y;

#pragma unroll
    for (int t0 = 0; t0 < CLEN; t0 += 8) {
        float2 g[8], u[8];
#pragma unroll
        for (int j = 0; j < 8; j++) {
            const size_t off = (size_t)(t0 + j) * (HH / 2);
            g[j] = __half22float2(gp[off]);
            u[j] = __half22float2(up[off]);
        }
#pragma unroll
        for (int j = 0; j < 8; j++) {
            hc0 = fmaf(g[j].x, u[j].x - hc0, hc0);
            hc1 = fmaf(g[j].y, u[j].y - hc1, hc1);
            op[(size_t)(t0 + j) * (HH / 2)] = make_float2(hc0, hc1);
        }
    }
}

extern "C" void kernel_launch(void* const* d_in, const int* in_sizes, int n_in,
                              void* d_out, int out_size)
{
    const float* x  = (const float*)d_in[0];   // [B,T,D]
    const float* h0 = (const float*)d_in[1];   // [B,H]
    const float* Wz = (const float*)d_in[2];   // [H,D]
    const float* bz = (const float*)d_in[3];   // [H]
    const float* Wh = (const float*)d_in[4];   // [H,D]
    const float* bh = (const float*)d_in[5];   // [H]
    float* out = (float*)d_out;                // [B,T,H]

    cudaFuncSetAttribute(mingru_gemm_tc,
                         cudaFuncAttributeMaxDynamicSharedMemorySize, GEMM_SMEM);

    mingru_wprep_kernel<<<NN * DD / 256, 256>>>(Wz, Wh);
    mingru_xconv_kernel<<<MM * DD / 4 / 256, 256>>>(x);

    dim3 grid(2, MM / 128);
    mingru_gemm_tc<<<grid, 256, GEMM_SMEM>>>(bz, bh);

    const int pair_threads = BB * NCH * HH / 2;   // 131072
    mingru_scan_pass1<<<pair_threads / 256, 256>>>();
    mingru_scan_pass2<<<BB * HH * 32 / 256, 256>>>(h0);
    mingru_scan_pass3<<<pair_threads / 256, 256>>>(out);
}